// round 2
// baseline (speedup 1.0000x reference)
#include <cuda_runtime.h>
#include <math.h>

#define B_  4
#define T_  2048
#define C_  1024
#define H_  16
#define D_  64
#define C3_ 3072

typedef unsigned long long u64;

// ---- packed fp32x2 helpers (sm_100+ only; ptxas never auto-emits these) ----
__device__ __forceinline__ u64 pk2(float lo, float hi) {
    u64 r; asm("mov.b64 %0,{%1,%2};" : "=l"(r) : "f"(lo), "f"(hi)); return r;
}
__device__ __forceinline__ void upk2(u64 v, float& lo, float& hi) {
    asm("mov.b64 {%0,%1},%2;" : "=f"(lo), "=f"(hi) : "l"(v));
}
__device__ __forceinline__ void fma2(u64& d, u64 a, u64 b) {
    asm("fma.rn.f32x2 %0,%1,%2,%0;" : "+l"(d) : "l"(a), "l"(b));
}
__device__ __forceinline__ void mul2(u64& d, u64 a) {
    asm("mul.rn.f32x2 %0,%0,%1;" : "+l"(d) : "l"(a));
}

// Scratch (allocation-free): qkv [B,T,3C], y [B,T,C]
__device__ float g_qkv[(size_t)B_ * T_ * C3_];
__device__ float g_y[(size_t)B_ * T_ * C_];

// ---------------------------------------------------------------------------
// SGEMM: C[M,N] = A[M,K] @ B[K,N] + bias[N]
// 128x128 tile, BK=8, 256 threads, 8x8 microtile, f32x2 inner loop.
// ---------------------------------------------------------------------------
__global__ __launch_bounds__(256) void sgemm_bias(
    const float* __restrict__ A, const float* __restrict__ Bm,
    const float* __restrict__ bias, float* __restrict__ C,
    int M, int N, int K)
{
    __shared__ float As[8][132];
    __shared__ float Bs[8][128];

    const int tid  = threadIdx.x;
    const int arow = tid >> 1;
    const int acol = (tid & 1) << 2;
    const int brow = tid >> 5;
    const int bcol = (tid & 31) << 2;
    const int tx = tid & 15, ty = tid >> 4;

    const float* Ab = A  + (size_t)blockIdx.y * 128 * K;
    const float* Bb = Bm + (size_t)blockIdx.x * 128;

    u64 acc2[8][4];            // acc2[i][jp] = (acc[i][2jp], acc[i][2jp+1])
    const u64 z2 = 0ull;       // bit pattern of (0.f, 0.f)
    #pragma unroll
    for (int i = 0; i < 8; i++)
        #pragma unroll
        for (int jp = 0; jp < 4; jp++) acc2[i][jp] = z2;

    for (int k0 = 0; k0 < K; k0 += 8) {
        float4 a4 = *(const float4*)(Ab + (size_t)arow * K + k0 + acol);
        As[acol + 0][arow] = a4.x;
        As[acol + 1][arow] = a4.y;
        As[acol + 2][arow] = a4.z;
        As[acol + 3][arow] = a4.w;
        *(float4*)&Bs[brow][bcol] =
            *(const float4*)(Bb + (size_t)(k0 + brow) * N + bcol);
        __syncthreads();

        #pragma unroll
        for (int kk = 0; kk < 8; kk++) {
            float ar[8];
            *(float4*)&ar[0] = *(const float4*)&As[kk][ty * 8];
            *(float4*)&ar[4] = *(const float4*)&As[kk][ty * 8 + 4];
            u64 br2[4];
            {   // B pairs come free from LDS.128 (adjacent regs = f32x2 pair)
                ulonglong2 t0 = *(const ulonglong2*)&Bs[kk][tx * 8];
                ulonglong2 t1 = *(const ulonglong2*)&Bs[kk][tx * 8 + 4];
                br2[0] = t0.x; br2[1] = t0.y; br2[2] = t1.x; br2[3] = t1.y;
            }
            #pragma unroll
            for (int i = 0; i < 8; i++) {
                u64 a2 = pk2(ar[i], ar[i]);
                #pragma unroll
                for (int jp = 0; jp < 4; jp++) fma2(acc2[i][jp], a2, br2[jp]);
            }
        }
        __syncthreads();
    }

    #pragma unroll
    for (int i = 0; i < 8; i++) {
        size_t row = (size_t)blockIdx.y * 128 + ty * 8 + i;
        #pragma unroll
        for (int j = 0; j < 8; j += 4) {
            int col = blockIdx.x * 128 + tx * 8 + j;
            float l0, h0, l1, h1;
            upk2(acc2[i][j / 2],     l0, h0);
            upk2(acc2[i][j / 2 + 1], l1, h1);
            float4 o;
            o.x = l0 + bias[col + 0];
            o.y = h0 + bias[col + 1];
            o.z = l1 + bias[col + 2];
            o.w = h1 + bias[col + 3];
            *(float4*)(C + row * N + col) = o;
        }
    }
}

// ---------------------------------------------------------------------------
// Sparsemax over head dim (64) of K, in-place. Unchanged (already ~30us).
// ---------------------------------------------------------------------------
__global__ __launch_bounds__(256) void sparsemax_k(float* __restrict__ qkv)
{
    __shared__ float zb[4][64];
    __shared__ int   cnt2[4][2];
    __shared__ float sum2[4][2];

    const int tid  = threadIdx.x;
    const int r    = tid >> 6;
    const int lane = tid & 63;
    const size_t row = (size_t)blockIdx.x * 4 + r;
    const size_t bt  = row >> 4;
    const int    h   = (int)(row & 15);

    float* p = qkv + bt * C3_ + C_ + h * D_ + lane;
    float z = *p;
    zb[r][lane] = z;
    __syncthreads();

    float sumge = 0.f; int rank = 0;
    #pragma unroll
    for (int j = 0; j < 64; j++) {
        float zj = zb[r][j];
        bool ge = (zj > z) || (zj == z && j <= lane);
        sumge += ge ? zj : 0.f;
        rank  += ge ? 1 : 0;
    }
    int c = (1.f + (float)rank * z > sumge) ? 1 : 0;
    #pragma unroll
    for (int o = 16; o > 0; o >>= 1) c += __shfl_xor_sync(0xffffffffu, c, o);
    if ((tid & 31) == 0) cnt2[r][lane >> 5] = c;
    __syncthreads();
    int rho = cnt2[r][0] + cnt2[r][1];

    float zs = (rank <= rho) ? z : 0.f;
    #pragma unroll
    for (int o = 16; o > 0; o >>= 1) zs += __shfl_xor_sync(0xffffffffu, zs, o);
    if ((tid & 31) == 0) sum2[r][lane >> 5] = zs;
    __syncthreads();
    float cs  = sum2[r][0] + sum2[r][1];
    float tau = (cs - 1.f) / (float)rho;
    *p = fmaxf(z - tau, 0.f);
}

// ---------------------------------------------------------------------------
// Flash attention (causal) + fused XSA correction, f32x2 inner loops.
// Grid (T/128, H, B), 128 threads; one q row per thread.
// ---------------------------------------------------------------------------
__global__ __launch_bounds__(128) void flash_xsa(
    const float* __restrict__ qkv, float* __restrict__ y)
{
    __shared__ float4 ks[64][16];
    __shared__ float4 vs[64][16];

    const int b = blockIdx.z, h = blockIdx.y;
    const int tq = blockIdx.x * 128 + threadIdx.x;
    const size_t base = (size_t)b * T_ * C3_;

    u64 q2[32];    // packed q pairs
    {
        const float* qrow = qkv + base + (size_t)tq * C3_ + h * D_;
        #pragma unroll
        for (int dd = 0; dd < 16; dd++) {
            ulonglong2 t = *(const ulonglong2*)(qrow + dd * 4);
            q2[dd * 2] = t.x; q2[dd * 2 + 1] = t.y;
        }
    }

    u64 O2[32];
    #pragma unroll
    for (int i = 0; i < 32; i++) O2[i] = 0ull;
    float m = -1e30f, l = 0.f;

    const int ktiles = (blockIdx.x + 1) * 2;
    for (int kt = 0; kt < ktiles; kt++) {
        for (int i = threadIdx.x; i < 1024; i += 128) {
            int j = i >> 4, dd = i & 15;
            const float* kvp = qkv + base + (size_t)(kt * 64 + j) * C3_ + h * D_ + dd * 4;
            ks[j][dd] = *(const float4*)(kvp + C_);
            vs[j][dd] = *(const float4*)(kvp + 2 * C_);
        }
        __syncthreads();

        const int jlim = tq - kt * 64;
        if (jlim >= 0) {
            for (int j0 = 0; j0 < 64 && j0 <= jlim; j0 += 16) {
                float s[16], cmax = -1e30f;
                #pragma unroll
                for (int jj = 0; jj < 16; jj++) {
                    int j = j0 + jj;
                    u64 acc2 = 0ull;
                    const ulonglong2* kp = (const ulonglong2*)&ks[j][0];
                    #pragma unroll
                    for (int dd = 0; dd < 16; dd++) {
                        ulonglong2 k2 = kp[dd];
                        fma2(acc2, q2[dd * 2],     k2.x);
                        fma2(acc2, q2[dd * 2 + 1], k2.y);
                    }
                    float lo, hi; upk2(acc2, lo, hi);
                    float accv = lo + hi;
                    s[jj] = (j <= jlim) ? accv * 0.125f : -1e30f;
                    cmax = fmaxf(cmax, s[jj]);
                }
                float mnew = fmaxf(m, cmax);
                float corr = __expf(m - mnew);
                l *= corr;
                u64 corr2 = pk2(corr, corr);
                #pragma unroll
                for (int i = 0; i < 32; i++) mul2(O2[i], corr2);
                #pragma unroll
                for (int jj = 0; jj < 16; jj++) {
                    float p = __expf(s[jj] - mnew);
                    l += p;
                    u64 p2 = pk2(p, p);
                    int j = j0 + jj;
                    const ulonglong2* vp = (const ulonglong2*)&vs[j][0];
                    #pragma unroll
                    for (int dd = 0; dd < 16; dd++) {
                        ulonglong2 v2 = vp[dd];
                        fma2(O2[dd * 2],     p2, v2.x);
                        fma2(O2[dd * 2 + 1], p2, v2.y);
                    }
                }
                m = mnew;
            }
        }
        __syncthreads();
    }

    // finalize softmax + XSA correction
    float O[64];
    #pragma unroll
    for (int i = 0; i < 32; i++) upk2(O2[i], O[i * 2], O[i * 2 + 1]);

    float invl = 1.f / l;
    float vr[64];
    const float* vrow = qkv + base + (size_t)tq * C3_ + 2 * C_ + h * D_;
    #pragma unroll
    for (int dd = 0; dd < 16; dd++) {
        float4 v4 = *(const float4*)(vrow + dd * 4);
        vr[dd*4+0] = v4.x; vr[dd*4+1] = v4.y; vr[dd*4+2] = v4.z; vr[dd*4+3] = v4.w;
    }
    float vn = 0.f;
    #pragma unroll
    for (int d = 0; d < 64; d++) { O[d] *= invl; vn += vr[d] * vr[d]; }
    float inv_norm = 1.f / fmaxf(sqrtf(vn), 1e-12f);
    float coef = 0.f;
    #pragma unroll
    for (int d = 0; d < 64; d++) coef += O[d] * vr[d];
    coef *= inv_norm * inv_norm;

    float* yout = y + ((size_t)(b * T_ + tq)) * C_ + h * D_;
    #pragma unroll
    for (int dd = 0; dd < 16; dd++) {
        float4 o4;
        o4.x = O[dd*4+0] - coef * vr[dd*4+0];
        o4.y = O[dd*4+1] - coef * vr[dd*4+1];
        o4.z = O[dd*4+2] - coef * vr[dd*4+2];
        o4.w = O[dd*4+3] - coef * vr[dd*4+3];
        *(float4*)(yout + dd * 4) = o4;
    }
}

// ---------------------------------------------------------------------------
extern "C" void kernel_launch(void* const* d_in, const int* in_sizes, int n_in,
                              void* d_out, int out_size)
{
    const float* x  = (const float*)d_in[0];
    const float* Wa = (const float*)d_in[1];
    const float* ba = (const float*)d_in[2];
    const float* Wp = (const float*)d_in[3];
    const float* bp = (const float*)d_in[4];
    float* out = (float*)d_out;

    float *qkv, *yb;
    cudaGetSymbolAddress((void**)&qkv, g_qkv);
    cudaGetSymbolAddress((void**)&yb,  g_y);

    {   // qkv = x @ W_attn + b_attn
        dim3 grid(C3_ / 128, (B_ * T_) / 128);
        sgemm_bias<<<grid, 256>>>(x, Wa, ba, qkv, B_ * T_, C3_, C_);
    }
    sparsemax_k<<<(B_ * T_ * H_) / 4, 256>>>(qkv);
    {   // flash attention + XSA
        dim3 grid(T_ / 128, H_, B_);
        flash_xsa<<<grid, 128>>>(qkv, yb);
    }
    {   // out = y @ W_proj + b_proj
        dim3 grid(C_ / 128, (B_ * T_) / 128);
        sgemm_bias<<<grid, 256>>>(yb, Wp, bp, out, B_ * T_, C_, C_);
    }
}

// round 4
// speedup vs baseline: 1.3368x; 1.3368x over previous
#include <cuda_runtime.h>
#include <cuda_bf16.h>
#include <math.h>
#include <stdint.h>

#define B_  4
#define T_  2048
#define C_  1024
#define H_  16
#define D_  64
#define C3_ 3072
#define K3_ 3072          // split-bf16 tripled K

typedef unsigned long long u64;

// ---- scratch (allocation-free) ----
__device__ float g_qkv[(size_t)B_ * T_ * C3_];
__device__ float g_y[(size_t)B_ * T_ * C_];
__device__ __nv_bfloat16 g_A3[(size_t)B_ * T_ * K3_];   // [M, 3K] split A
__device__ __nv_bfloat16 g_B3[(size_t)C3_ * K3_];       // [N, 3K] split+transposed W

// ---- helpers ----
__device__ __forceinline__ uint32_t smem_u32(const void* p) {
    uint32_t a;
    asm("{ .reg .u64 t; cvta.to.shared.u64 t, %1; cvt.u32.u64 %0, t; }" : "=r"(a) : "l"(p));
    return a;
}
__device__ __forceinline__ void cp16(uint32_t dst, const void* src) {
    asm volatile("cp.async.cg.shared.global [%0], [%1], 16;" :: "r"(dst), "l"(src));
}
__device__ __forceinline__ void ldsm_x4(uint32_t& r0, uint32_t& r1, uint32_t& r2, uint32_t& r3,
                                        uint32_t addr) {
    asm volatile("ldmatrix.sync.aligned.m8n8.x4.shared.b16 {%0,%1,%2,%3},[%4];"
                 : "=r"(r0), "=r"(r1), "=r"(r2), "=r"(r3) : "r"(addr));
}
__device__ __forceinline__ void mma16816(float* c, const uint32_t* a, uint32_t b0, uint32_t b1) {
    asm volatile(
        "mma.sync.aligned.m16n8k16.row.col.f32.bf16.bf16.f32 "
        "{%0,%1,%2,%3},{%4,%5,%6,%7},{%8,%9},{%0,%1,%2,%3};"
        : "+f"(c[0]), "+f"(c[1]), "+f"(c[2]), "+f"(c[3])
        : "r"(a[0]), "r"(a[1]), "r"(a[2]), "r"(a[3]), "r"(b0), "r"(b1));
}

// ---------------------------------------------------------------------------
// split_A: src fp32 [M,1024] -> dst bf16 [M,3072] blocks [hi | lo | hi]
// ---------------------------------------------------------------------------
__global__ __launch_bounds__(256) void split_A(
    const float* __restrict__ src, __nv_bfloat16* __restrict__ dst)
{
    size_t idx = (size_t)blockIdx.x * 256 + threadIdx.x;   // over M*1024
    int m = (int)(idx >> 10), k = (int)(idx & 1023);
    float a = src[idx];
    __nv_bfloat16 hi = __float2bfloat16(a);
    __nv_bfloat16 lo = __float2bfloat16(a - __bfloat162float(hi));
    size_t r = (size_t)m * K3_;
    dst[r + k]        = hi;
    dst[r + 1024 + k] = lo;
    dst[r + 2048 + k] = hi;
}

// ---------------------------------------------------------------------------
// prep_W: W fp32 [1024, N] -> Bo bf16 [N, 3072] blocks [hi | hi | lo] (transposed)
// ---------------------------------------------------------------------------
__global__ __launch_bounds__(256) void prep_W(
    const float* __restrict__ W, __nv_bfloat16* __restrict__ Bo, int N)
{
    __shared__ float t[32][33];
    int n0 = blockIdx.x * 32, k0 = blockIdx.y * 32;
    int tx = threadIdx.x & 31, ty = threadIdx.x >> 5;   // 32 x 8
    #pragma unroll
    for (int i = 0; i < 4; i++)
        t[ty + i * 8][tx] = W[(size_t)(k0 + ty + i * 8) * N + n0 + tx];
    __syncthreads();
    #pragma unroll
    for (int i = 0; i < 4; i++) {
        float w = t[tx][ty + i * 8];
        __nv_bfloat16 hi = __float2bfloat16(w);
        __nv_bfloat16 lo = __float2bfloat16(w - __bfloat162float(hi));
        size_t r = (size_t)(n0 + ty + i * 8) * K3_;
        Bo[r + k0 + tx]        = hi;
        Bo[r + 1024 + k0 + tx] = hi;
        Bo[r + 2048 + k0 + tx] = lo;
    }
}

// ---------------------------------------------------------------------------
// HMMA GEMM: Cout[M,N] = A3[M,K3] * B3[N,K3]^T + bias, fp32 accumulate.
// 128x128 CTA tile, BK=32, 256 threads (8 warps of 64x32), mma.sync bf16,
// double-buffered cp.async. Smem rows padded to 40 bf16 (80B) -> conflict-free
// ldmatrix.
// ---------------------------------------------------------------------------
#define BK   32
#define ROWE 40   // bf16 elements per smem row (32 data + 8 pad)

__global__ __launch_bounds__(256) void hmma_gemm(
    const __nv_bfloat16* __restrict__ A, const __nv_bfloat16* __restrict__ Bk,
    const float* __restrict__ bias, float* __restrict__ Cout,
    int M, int N, int K)
{
    __shared__ __nv_bfloat16 sA[2][128 * ROWE];
    __shared__ __nv_bfloat16 sB[2][128 * ROWE];

    const int tid  = threadIdx.x;
    const int lane = tid & 31;
    const int wid  = tid >> 5;
    const int wm   = wid >> 2;          // 0..1 -> m offset wm*64
    const int wn   = wid & 3;           // 0..3 -> n offset wn*32
    const int m0 = blockIdx.y * 128, n0 = blockIdx.x * 128;

    const uint32_t sA_b = smem_u32(&sA[0][0]);
    const uint32_t sB_b = smem_u32(&sB[0][0]);
    const uint32_t bufbytes = 128 * ROWE * 2;

    // load indexing: 512 16B-chunks per operand tile; thread covers 2 chunks
    const int lrow0 = tid >> 1;                 // chunks 2*tid, 2*tid+1 -> row tid>>1? no:
    // chunk c: row = c>>2, seg = c&3. c = tid and c = tid+256.
    auto load_tile = [&](int buf, int kt) {
        const __nv_bfloat16* Ag = A + (size_t)m0 * K + kt * BK;
        const __nv_bfloat16* Bg = Bk + (size_t)n0 * K + kt * BK;
        #pragma unroll
        for (int it = 0; it < 2; it++) {
            int c = tid + it * 256;
            int row = c >> 2, seg = c & 3;
            uint32_t doff = (uint32_t)(row * ROWE + seg * 8) * 2;
            cp16(sA_b + buf * bufbytes + doff, Ag + (size_t)row * K + seg * 8);
            cp16(sB_b + buf * bufbytes + doff, Bg + (size_t)row * K + seg * 8);
        }
        asm volatile("cp.async.commit_group;" ::: "memory");
    };

    float acc[4][4][4];
    #pragma unroll
    for (int i = 0; i < 4; i++)
        #pragma unroll
        for (int j = 0; j < 4; j++)
            #pragma unroll
            for (int e = 0; e < 4; e++) acc[i][j][e] = 0.f;

    const int nkt = K / BK;
    load_tile(0, 0);

    // ldmatrix lane-address components (element offsets within a tile)
    const int a_row = wm * 64 + (lane & 15);          // + mi*16
    const int a_ko  = (lane >> 4) * 8;                // + ks*16
    const int b_row = wn * 32 + (lane & 7) + ((lane >> 4) & 1) * 8;  // + nb*16
    const int b_ko  = ((lane >> 3) & 1) * 8;

    for (int kt = 0; kt < nkt; kt++) {
        if (kt + 1 < nkt) load_tile((kt + 1) & 1, kt + 1);
        else asm volatile("cp.async.commit_group;" ::: "memory");
        asm volatile("cp.async.wait_group 1;" ::: "memory");
        __syncthreads();

        const uint32_t aT = sA_b + (kt & 1) * bufbytes;
        const uint32_t bT = sB_b + (kt & 1) * bufbytes;

        #pragma unroll
        for (int ks = 0; ks < 2; ks++) {
            uint32_t af[4][4];
            #pragma unroll
            for (int mi = 0; mi < 4; mi++)
                ldsm_x4(af[mi][0], af[mi][1], af[mi][2], af[mi][3],
                        aT + (uint32_t)((a_row + mi * 16) * ROWE + ks * 16 + a_ko) * 2);
            uint32_t bf[4][2];
            #pragma unroll
            for (int nb = 0; nb < 2; nb++) {
                uint32_t r0, r1, r2, r3;
                ldsm_x4(r0, r1, r2, r3,
                        bT + (uint32_t)((b_row + nb * 16) * ROWE + ks * 16 + b_ko) * 2);
                bf[nb * 2][0] = r0; bf[nb * 2][1] = r1;
                bf[nb * 2 + 1][0] = r2; bf[nb * 2 + 1][1] = r3;
            }
            #pragma unroll
            for (int mi = 0; mi < 4; mi++)
                #pragma unroll
                for (int ni = 0; ni < 4; ni++)
                    mma16816(acc[mi][ni], af[mi], bf[ni][0], bf[ni][1]);
        }
        __syncthreads();
    }

    // epilogue
    #pragma unroll
    for (int mi = 0; mi < 4; mi++) {
        int row_g = m0 + wm * 64 + mi * 16 + (lane >> 2);
        #pragma unroll
        for (int ni = 0; ni < 4; ni++) {
            int col_g = n0 + wn * 32 + ni * 8 + (lane & 3) * 2;
            float b0 = bias[col_g], b1 = bias[col_g + 1];
            float2 o0 = make_float2(acc[mi][ni][0] + b0, acc[mi][ni][1] + b1);
            float2 o1 = make_float2(acc[mi][ni][2] + b0, acc[mi][ni][3] + b1);
            *(float2*)(Cout + (size_t)row_g * N + col_g) = o0;
            *(float2*)(Cout + (size_t)(row_g + 8) * N + col_g) = o1;
        }
    }
}

// ---------------------------------------------------------------------------
// Sparsemax over head dim (64) of K, in-place (unchanged).
// ---------------------------------------------------------------------------
__global__ __launch_bounds__(256) void sparsemax_k(float* __restrict__ qkv)
{
    __shared__ float zb[4][64];
    __shared__ int   cnt2[4][2];
    __shared__ float sum2[4][2];

    const int tid  = threadIdx.x;
    const int r    = tid >> 6;
    const int lane = tid & 63;
    const size_t row = (size_t)blockIdx.x * 4 + r;
    const size_t bt  = row >> 4;
    const int    h   = (int)(row & 15);

    float* p = qkv + bt * C3_ + C_ + h * D_ + lane;
    float z = *p;
    zb[r][lane] = z;
    __syncthreads();

    float sumge = 0.f; int rank = 0;
    #pragma unroll
    for (int j = 0; j < 64; j++) {
        float zj = zb[r][j];
        bool ge = (zj > z) || (zj == z && j <= lane);
        sumge += ge ? zj : 0.f;
        rank  += ge ? 1 : 0;
    }
    int c = (1.f + (float)rank * z > sumge) ? 1 : 0;
    #pragma unroll
    for (int o = 16; o > 0; o >>= 1) c += __shfl_xor_sync(0xffffffffu, c, o);
    if ((tid & 31) == 0) cnt2[r][lane >> 5] = c;
    __syncthreads();
    int rho = cnt2[r][0] + cnt2[r][1];

    float zs = (rank <= rho) ? z : 0.f;
    #pragma unroll
    for (int o = 16; o > 0; o >>= 1) zs += __shfl_xor_sync(0xffffffffu, zs, o);
    if ((tid & 31) == 0) sum2[r][lane >> 5] = zs;
    __syncthreads();
    float cs  = sum2[r][0] + sum2[r][1];
    float tau = (cs - 1.f) / (float)rho;
    *p = fmaxf(z - tau, 0.f);
}

// ---------------------------------------------------------------------------
// Flash attention (causal) + fused XSA correction (f32x2 version, unchanged).
// ---------------------------------------------------------------------------
__device__ __forceinline__ u64 pk2(float lo, float hi) {
    u64 r; asm("mov.b64 %0,{%1,%2};" : "=l"(r) : "f"(lo), "f"(hi)); return r;
}
__device__ __forceinline__ void upk2(u64 v, float& lo, float& hi) {
    asm("mov.b64 {%0,%1},%2;" : "=f"(lo), "=f"(hi) : "l"(v));
}
__device__ __forceinline__ void fma2(u64& d, u64 a, u64 b) {
    asm("fma.rn.f32x2 %0,%1,%2,%0;" : "+l"(d) : "l"(a), "l"(b));
}
__device__ __forceinline__ void mul2(u64& d, u64 a) {
    asm("mul.rn.f32x2 %0,%0,%1;" : "+l"(d) : "l"(a));
}

__global__ __launch_bounds__(128) void flash_xsa(
    const float* __restrict__ qkv, float* __restrict__ y)
{
    __shared__ float4 ks[64][16];
    __shared__ float4 vs[64][16];

    const int b = blockIdx.z, h = blockIdx.y;
    const int tq = blockIdx.x * 128 + threadIdx.x;
    const size_t base = (size_t)b * T_ * C3_;

    u64 q2[32];
    {
        const float* qrow = qkv + base + (size_t)tq * C3_ + h * D_;
        #pragma unroll
        for (int dd = 0; dd < 16; dd++) {
            ulonglong2 t = *(const ulonglong2*)(qrow + dd * 4);
            q2[dd * 2] = t.x; q2[dd * 2 + 1] = t.y;
        }
    }

    u64 O2[32];
    #pragma unroll
    for (int i = 0; i < 32; i++) O2[i] = 0ull;
    float m = -1e30f, l = 0.f;

    const int ktiles = (blockIdx.x + 1) * 2;
    for (int kt = 0; kt < ktiles; kt++) {
        for (int i = threadIdx.x; i < 1024; i += 128) {
            int j = i >> 4, dd = i & 15;
            const float* kvp = qkv + base + (size_t)(kt * 64 + j) * C3_ + h * D_ + dd * 4;
            ks[j][dd] = *(const float4*)(kvp + C_);
            vs[j][dd] = *(const float4*)(kvp + 2 * C_);
        }
        __syncthreads();

        const int jlim = tq - kt * 64;
        if (jlim >= 0) {
            for (int j0 = 0; j0 < 64 && j0 <= jlim; j0 += 16) {
                float s[16], cmax = -1e30f;
                #pragma unroll
                for (int jj = 0; jj < 16; jj++) {
                    int j = j0 + jj;
                    u64 acc2 = 0ull;
                    const ulonglong2* kp = (const ulonglong2*)&ks[j][0];
                    #pragma unroll
                    for (int dd = 0; dd < 16; dd++) {
                        ulonglong2 k2 = kp[dd];
                        fma2(acc2, q2[dd * 2],     k2.x);
                        fma2(acc2, q2[dd * 2 + 1], k2.y);
                    }
                    float lo, hi; upk2(acc2, lo, hi);
                    float accv = lo + hi;
                    s[jj] = (j <= jlim) ? accv * 0.125f : -1e30f;
                    cmax = fmaxf(cmax, s[jj]);
                }
                float mnew = fmaxf(m, cmax);
                float corr = __expf(m - mnew);
                l *= corr;
                u64 corr2 = pk2(corr, corr);
                #pragma unroll
                for (int i = 0; i < 32; i++) mul2(O2[i], corr2);
                #pragma unroll
                for (int jj = 0; jj < 16; jj++) {
                    float p = __expf(s[jj] - mnew);
                    l += p;
                    u64 p2 = pk2(p, p);
                    int j = j0 + jj;
                    const ulonglong2* vp = (const ulonglong2*)&vs[j][0];
                    #pragma unroll
                    for (int dd = 0; dd < 16; dd++) {
                        ulonglong2 v2 = vp[dd];
                        fma2(O2[dd * 2],     p2, v2.x);
                        fma2(O2[dd * 2 + 1], p2, v2.y);
                    }
                }
                m = mnew;
            }
        }
        __syncthreads();
    }

    float O[64];
    #pragma unroll
    for (int i = 0; i < 32; i++) upk2(O2[i], O[i * 2], O[i * 2 + 1]);

    float invl = 1.f / l;
    float vr[64];
    const float* vrow = qkv + base + (size_t)tq * C3_ + 2 * C_ + h * D_;
    #pragma unroll
    for (int dd = 0; dd < 16; dd++) {
        float4 v4 = *(const float4*)(vrow + dd * 4);
        vr[dd*4+0] = v4.x; vr[dd*4+1] = v4.y; vr[dd*4+2] = v4.z; vr[dd*4+3] = v4.w;
    }
    float vn = 0.f;
    #pragma unroll
    for (int d = 0; d < 64; d++) { O[d] *= invl; vn += vr[d] * vr[d]; }
    float inv_norm = 1.f / fmaxf(sqrtf(vn), 1e-12f);
    float coef = 0.f;
    #pragma unroll
    for (int d = 0; d < 64; d++) coef += O[d] * vr[d];
    coef *= inv_norm * inv_norm;

    float* yout = y + ((size_t)(b * T_ + tq)) * C_ + h * D_;
    #pragma unroll
    for (int dd = 0; dd < 16; dd++) {
        float4 o4;
        o4.x = O[dd*4+0] - coef * vr[dd*4+0];
        o4.y = O[dd*4+1] - coef * vr[dd*4+1];
        o4.z = O[dd*4+2] - coef * vr[dd*4+2];
        o4.w = O[dd*4+3] - coef * vr[dd*4+3];
        *(float4*)(yout + dd * 4) = o4;
    }
}

// ---------------------------------------------------------------------------
extern "C" void kernel_launch(void* const* d_in, const int* in_sizes, int n_in,
                              void* d_out, int out_size)
{
    const float* x  = (const float*)d_in[0];
    const float* Wa = (const float*)d_in[1];
    const float* ba = (const float*)d_in[2];
    const float* Wp = (const float*)d_in[3];
    const float* bp = (const float*)d_in[4];
    float* out = (float*)d_out;

    float *qkv, *yb;
    __nv_bfloat16 *A3, *B3;
    cudaGetSymbolAddress((void**)&qkv, g_qkv);
    cudaGetSymbolAddress((void**)&yb,  g_y);
    cudaGetSymbolAddress((void**)&A3,  g_A3);
    cudaGetSymbolAddress((void**)&B3,  g_B3);

    const int M = B_ * T_;   // 8192

    // --- QKV GEMM: qkv = x @ W_attn + b_attn via split-bf16 HMMA ---
    prep_W<<<dim3(C3_ / 32, C_ / 32), 256>>>(Wa, B3, C3_);
    split_A<<<(M * C_) / 256, 256>>>(x, A3);
    hmma_gemm<<<dim3(C3_ / 128, M / 128), 256>>>(A3, B3, ba, qkv, M, C3_, K3_);

    // --- sparsemax on K ---
    sparsemax_k<<<(M * H_) / 4, 256>>>(qkv);

    // --- flash attention + XSA ---
    {
        dim3 grid(T_ / 128, H_, B_);
        flash_xsa<<<grid, 128>>>(qkv, yb);
    }

    // --- projection GEMM: out = y @ W_proj + b_proj ---
    prep_W<<<dim3(C_ / 32, C_ / 32), 256>>>(Wp, B3, C_);
    split_A<<<(M * C_) / 256, 256>>>(yb, A3);
    hmma_gemm<<<dim3(C_ / 128, M / 128), 256>>>(A3, B3, bp, out, M, C_, K3_);
}

// round 5
// speedup vs baseline: 2.4827x; 1.8572x over previous
#include <cuda_runtime.h>
#include <cuda_bf16.h>
#include <math.h>
#include <stdint.h>

#define B_  4
#define T_  2048
#define C_  1024
#define H_  16
#define D_  64
#define C3_ 3072
#define K3_ 3072

typedef unsigned long long u64;

__device__ float g_qkv[(size_t)B_ * T_ * C3_];
__device__ float g_y[(size_t)B_ * T_ * C_];
__device__ __nv_bfloat16 g_A3[(size_t)B_ * T_ * K3_];
__device__ __nv_bfloat16 g_B3[(size_t)C3_ * K3_];

// ---- helpers ----
__device__ __forceinline__ uint32_t smem_u32(const void* p) {
    uint32_t a;
    asm("{ .reg .u64 t; cvta.to.shared.u64 t, %1; cvt.u32.u64 %0, t; }" : "=r"(a) : "l"(p));
    return a;
}
__device__ __forceinline__ void cp16(uint32_t dst, const void* src) {
    asm volatile("cp.async.cg.shared.global [%0], [%1], 16;" :: "r"(dst), "l"(src));
}
__device__ __forceinline__ void ldsm_x4(uint32_t& r0, uint32_t& r1, uint32_t& r2, uint32_t& r3,
                                        uint32_t addr) {
    asm volatile("ldmatrix.sync.aligned.m8n8.x4.shared.b16 {%0,%1,%2,%3},[%4];"
                 : "=r"(r0), "=r"(r1), "=r"(r2), "=r"(r3) : "r"(addr));
}
__device__ __forceinline__ void ldsm_x4t(uint32_t& r0, uint32_t& r1, uint32_t& r2, uint32_t& r3,
                                         uint32_t addr) {
    asm volatile("ldmatrix.sync.aligned.m8n8.x4.trans.shared.b16 {%0,%1,%2,%3},[%4];"
                 : "=r"(r0), "=r"(r1), "=r"(r2), "=r"(r3) : "r"(addr));
}
__device__ __forceinline__ void mma16816(float* c, const uint32_t* a, uint32_t b0, uint32_t b1) {
    asm volatile(
        "mma.sync.aligned.m16n8k16.row.col.f32.bf16.bf16.f32 "
        "{%0,%1,%2,%3},{%4,%5,%6,%7},{%8,%9},{%0,%1,%2,%3};"
        : "+f"(c[0]), "+f"(c[1]), "+f"(c[2]), "+f"(c[3])
        : "r"(a[0]), "r"(a[1]), "r"(a[2]), "r"(a[3]), "r"(b0), "r"(b1));
}
__device__ __forceinline__ uint32_t pkbf(float lo, float hi) {  // low half = lo
    uint32_t r; asm("cvt.rn.bf16x2.f32 %0,%1,%2;" : "=r"(r) : "f"(hi), "f"(lo)); return r;
}

// ---------------------------------------------------------------------------
// split_A / prep_W (unchanged from r4)
// ---------------------------------------------------------------------------
__global__ __launch_bounds__(256) void split_A(
    const float* __restrict__ src, __nv_bfloat16* __restrict__ dst)
{
    size_t idx = (size_t)blockIdx.x * 256 + threadIdx.x;
    int m = (int)(idx >> 10), k = (int)(idx & 1023);
    float a = src[idx];
    __nv_bfloat16 hi = __float2bfloat16(a);
    __nv_bfloat16 lo = __float2bfloat16(a - __bfloat162float(hi));
    size_t r = (size_t)m * K3_;
    dst[r + k] = hi; dst[r + 1024 + k] = lo; dst[r + 2048 + k] = hi;
}

__global__ __launch_bounds__(256) void prep_W(
    const float* __restrict__ W, __nv_bfloat16* __restrict__ Bo, int N)
{
    __shared__ float t[32][33];
    int n0 = blockIdx.x * 32, k0 = blockIdx.y * 32;
    int tx = threadIdx.x & 31, ty = threadIdx.x >> 5;
    #pragma unroll
    for (int i = 0; i < 4; i++)
        t[ty + i * 8][tx] = W[(size_t)(k0 + ty + i * 8) * N + n0 + tx];
    __syncthreads();
    #pragma unroll
    for (int i = 0; i < 4; i++) {
        float w = t[tx][ty + i * 8];
        __nv_bfloat16 hi = __float2bfloat16(w);
        __nv_bfloat16 lo = __float2bfloat16(w - __bfloat162float(hi));
        size_t r = (size_t)(n0 + ty + i * 8) * K3_;
        Bo[r + k0 + tx] = hi; Bo[r + 1024 + k0 + tx] = hi; Bo[r + 2048 + k0 + tx] = lo;
    }
}

// ---------------------------------------------------------------------------
// HMMA GEMM (unchanged from r4)
// ---------------------------------------------------------------------------
#define BK   32
#define ROWE 40

__global__ __launch_bounds__(256) void hmma_gemm(
    const __nv_bfloat16* __restrict__ A, const __nv_bfloat16* __restrict__ Bk,
    const float* __restrict__ bias, float* __restrict__ Cout,
    int M, int N, int K)
{
    __shared__ __nv_bfloat16 sA[2][128 * ROWE];
    __shared__ __nv_bfloat16 sB[2][128 * ROWE];

    const int tid  = threadIdx.x;
    const int lane = tid & 31;
    const int wid  = tid >> 5;
    const int wm   = wid >> 2;
    const int wn   = wid & 3;
    const int m0 = blockIdx.y * 128, n0 = blockIdx.x * 128;

    const uint32_t sA_b = smem_u32(&sA[0][0]);
    const uint32_t sB_b = smem_u32(&sB[0][0]);
    const uint32_t bufbytes = 128 * ROWE * 2;

    auto load_tile = [&](int buf, int kt) {
        const __nv_bfloat16* Ag = A + (size_t)m0 * K + kt * BK;
        const __nv_bfloat16* Bg = Bk + (size_t)n0 * K + kt * BK;
        #pragma unroll
        for (int it = 0; it < 2; it++) {
            int c = tid + it * 256;
            int row = c >> 2, seg = c & 3;
            uint32_t doff = (uint32_t)(row * ROWE + seg * 8) * 2;
            cp16(sA_b + buf * bufbytes + doff, Ag + (size_t)row * K + seg * 8);
            cp16(sB_b + buf * bufbytes + doff, Bg + (size_t)row * K + seg * 8);
        }
        asm volatile("cp.async.commit_group;" ::: "memory");
    };

    float acc[4][4][4];
    #pragma unroll
    for (int i = 0; i < 4; i++)
        #pragma unroll
        for (int j = 0; j < 4; j++)
            #pragma unroll
            for (int e = 0; e < 4; e++) acc[i][j][e] = 0.f;

    const int nkt = K / BK;
    load_tile(0, 0);

    const int a_row = wm * 64 + (lane & 15);
    const int a_ko  = (lane >> 4) * 8;
    const int b_row = wn * 32 + (lane & 7) + ((lane >> 4) & 1) * 8;
    const int b_ko  = ((lane >> 3) & 1) * 8;

    for (int kt = 0; kt < nkt; kt++) {
        if (kt + 1 < nkt) load_tile((kt + 1) & 1, kt + 1);
        else asm volatile("cp.async.commit_group;" ::: "memory");
        asm volatile("cp.async.wait_group 1;" ::: "memory");
        __syncthreads();

        const uint32_t aT = sA_b + (kt & 1) * bufbytes;
        const uint32_t bT = sB_b + (kt & 1) * bufbytes;

        #pragma unroll
        for (int ks = 0; ks < 2; ks++) {
            uint32_t af[4][4];
            #pragma unroll
            for (int mi = 0; mi < 4; mi++)
                ldsm_x4(af[mi][0], af[mi][1], af[mi][2], af[mi][3],
                        aT + (uint32_t)((a_row + mi * 16) * ROWE + ks * 16 + a_ko) * 2);
            uint32_t bf[4][2];
            #pragma unroll
            for (int nb = 0; nb < 2; nb++) {
                uint32_t r0, r1, r2, r3;
                ldsm_x4(r0, r1, r2, r3,
                        bT + (uint32_t)((b_row + nb * 16) * ROWE + ks * 16 + b_ko) * 2);
                bf[nb * 2][0] = r0; bf[nb * 2][1] = r1;
                bf[nb * 2 + 1][0] = r2; bf[nb * 2 + 1][1] = r3;
            }
            #pragma unroll
            for (int mi = 0; mi < 4; mi++)
                #pragma unroll
                for (int ni = 0; ni < 4; ni++)
                    mma16816(acc[mi][ni], af[mi], bf[ni][0], bf[ni][1]);
        }
        __syncthreads();
    }

    #pragma unroll
    for (int mi = 0; mi < 4; mi++) {
        int row_g = m0 + wm * 64 + mi * 16 + (lane >> 2);
        #pragma unroll
        for (int ni = 0; ni < 4; ni++) {
            int col_g = n0 + wn * 32 + ni * 8 + (lane & 3) * 2;
            float b0 = bias[col_g], b1 = bias[col_g + 1];
            float2 o0 = make_float2(acc[mi][ni][0] + b0, acc[mi][ni][1] + b1);
            float2 o1 = make_float2(acc[mi][ni][2] + b0, acc[mi][ni][3] + b1);
            *(float2*)(Cout + (size_t)row_g * N + col_g) = o0;
            *(float2*)(Cout + (size_t)(row_g + 8) * N + col_g) = o1;
        }
    }
}

// ---------------------------------------------------------------------------
// Sparsemax (unchanged)
// ---------------------------------------------------------------------------
__global__ __launch_bounds__(256) void sparsemax_k(float* __restrict__ qkv)
{
    __shared__ float zb[4][64];
    __shared__ int   cnt2[4][2];
    __shared__ float sum2[4][2];

    const int tid  = threadIdx.x;
    const int r    = tid >> 6;
    const int lane = tid & 63;
    const size_t row = (size_t)blockIdx.x * 4 + r;
    const size_t bt  = row >> 4;
    const int    h   = (int)(row & 15);

    float* p = qkv + bt * C3_ + C_ + h * D_ + lane;
    float z = *p;
    zb[r][lane] = z;
    __syncthreads();

    float sumge = 0.f; int rank = 0;
    #pragma unroll
    for (int j = 0; j < 64; j++) {
        float zj = zb[r][j];
        bool ge = (zj > z) || (zj == z && j <= lane);
        sumge += ge ? zj : 0.f;
        rank  += ge ? 1 : 0;
    }
    int c = (1.f + (float)rank * z > sumge) ? 1 : 0;
    #pragma unroll
    for (int o = 16; o > 0; o >>= 1) c += __shfl_xor_sync(0xffffffffu, c, o);
    if ((tid & 31) == 0) cnt2[r][lane >> 5] = c;
    __syncthreads();
    int rho = cnt2[r][0] + cnt2[r][1];

    float zs = (rank <= rho) ? z : 0.f;
    #pragma unroll
    for (int o = 16; o > 0; o >>= 1) zs += __shfl_xor_sync(0xffffffffu, zs, o);
    if ((tid & 31) == 0) sum2[r][lane >> 5] = zs;
    __syncthreads();
    float cs  = sum2[r][0] + sum2[r][1];
    float tau = (cs - 1.f) / (float)rho;
    *p = fmaxf(z - tau, 0.f);
}

// ---------------------------------------------------------------------------
// Flash attention on tensor cores (split-bf16) + fused XSA correction.
// Grid (16, H, B), 256 threads (8 warps). Warp w owns q rows w*16..w*16+15.
// Q' = [Qh|Ql] (scale folded), K' = [Kh|Kl], V' = [Vh|Vl] in smem.
// 3-term products: Qh·Kh + Ql·Kh + Qh·Kl ; Ph·Vh + Pl·Vh + Ph·Vl.
// ---------------------------------------------------------------------------
#define FROW 136

__global__ __launch_bounds__(256) void flash_hmma(
    const float* __restrict__ qkv, float* __restrict__ y)
{
    __shared__ __nv_bfloat16 sm[128 * FROW];   // Q staging; later K rows 0..63, V rows 64..127

    const int tid  = threadIdx.x;
    const int lane = tid & 31;
    const int w    = tid >> 5;
    const int qt = blockIdx.x, h = blockIdx.y, b = blockIdx.z;
    const size_t base = (size_t)b * T_ * C3_;

    // ---- stage Q (scaled by 1/8) as [hi|lo], then grab A-fragments ----
    for (int i = tid; i < 2048; i += 256) {           // 128 rows x 16 float4
        int row = i >> 4, d = (i & 15) * 4;
        float4 f4 = *(const float4*)(qkv + base + (size_t)(qt * 128 + row) * C3_ + h * D_ + d);
        float f[4] = {f4.x * 0.125f, f4.y * 0.125f, f4.z * 0.125f, f4.w * 0.125f};
        #pragma unroll
        for (int j = 0; j < 4; j++) {
            __nv_bfloat16 hi = __float2bfloat16(f[j]);
            sm[row * FROW + d + j]      = hi;
            sm[row * FROW + 64 + d + j] = __float2bfloat16(f[j] - __bfloat162float(hi));
        }
    }
    __syncthreads();

    uint32_t qf[8][4];
    #pragma unroll
    for (int kb = 0; kb < 8; kb++) {
        uint32_t addr = smem_u32(&sm[(w * 16 + (lane & 15)) * FROW + kb * 16 + (lane >> 4) * 8]);
        ldsm_x4(qf[kb][0], qf[kb][1], qf[kb][2], qf[kb][3], addr);
    }
    __syncthreads();   // Q consumed; smem now free for K/V

    float o[8][4];
    #pragma unroll
    for (int nb = 0; nb < 8; nb++)
        #pragma unroll
        for (int e = 0; e < 4; e++) o[nb][e] = 0.f;
    float m0 = -1e30f, m1 = -1e30f, l0 = 0.f, l1 = 0.f;

    const int qrow_g0 = qt * 128 + w * 16 + (lane >> 2);
    const int nkt = (qt + 1) * 2;

    for (int kt = 0; kt < nkt; kt++) {
        // ---- load + split K (rows 0..63) and V (rows 64..127) ----
        for (int i = tid; i < 1024; i += 256) {       // 64 rows x 16 float4
            int row = i >> 4, d = (i & 15) * 4;
            const float* kp = qkv + base + (size_t)(kt * 64 + row) * C3_ + C_ + h * D_ + d;
            float4 k4 = *(const float4*)kp;
            float4 v4 = *(const float4*)(kp + C_);
            #pragma unroll
            for (int j = 0; j < 4; j++) {
                float kv = (&k4.x)[j], vv = (&v4.x)[j];
                __nv_bfloat16 kh = __float2bfloat16(kv);
                __nv_bfloat16 vh = __float2bfloat16(vv);
                sm[row * FROW + d + j]              = kh;
                sm[row * FROW + 64 + d + j]         = __float2bfloat16(kv - __bfloat162float(kh));
                sm[(64 + row) * FROW + d + j]       = vh;
                sm[(64 + row) * FROW + 64 + d + j]  = __float2bfloat16(vv - __bfloat162float(vh));
            }
        }
        __syncthreads();

        // ---- S = Q' K'^T ----
        float s[8][4];
        #pragma unroll
        for (int nb = 0; nb < 8; nb++)
            #pragma unroll
            for (int e = 0; e < 4; e++) s[nb][e] = 0.f;

        #pragma unroll
        for (int kb = 0; kb < 12; kb++) {
            int bcol = (kb < 4) ? kb * 16 : ((kb < 8) ? (kb - 4) * 16 : 64 + (kb - 8) * 16);
            const uint32_t* af = (kb < 8) ? qf[kb] : qf[kb - 8];
            #pragma unroll
            for (int nbp = 0; nbp < 4; nbp++) {
                uint32_t r0, r1, r2, r3;
                uint32_t addr = smem_u32(&sm[(nbp * 16 + (lane & 7) + ((lane >> 4) & 1) * 8) * FROW
                                             + bcol + ((lane >> 3) & 1) * 8]);
                ldsm_x4(r0, r1, r2, r3, addr);
                mma16816(s[nbp * 2],     af, r0, r1);
                mma16816(s[nbp * 2 + 1], af, r2, r3);
            }
        }

        // ---- causal mask ----
        if (kt * 64 + 63 > qt * 128 + w * 16) {
            #pragma unroll
            for (int nb = 0; nb < 8; nb++) {
                int col = kt * 64 + nb * 8 + (lane & 3) * 2;
                if (col     > qrow_g0)     s[nb][0] = -1e30f;
                if (col + 1 > qrow_g0)     s[nb][1] = -1e30f;
                if (col     > qrow_g0 + 8) s[nb][2] = -1e30f;
                if (col + 1 > qrow_g0 + 8) s[nb][3] = -1e30f;
            }
        }

        // ---- online softmax ----
        float tm0 = -1e30f, tm1 = -1e30f;
        #pragma unroll
        for (int nb = 0; nb < 8; nb++) {
            tm0 = fmaxf(tm0, fmaxf(s[nb][0], s[nb][1]));
            tm1 = fmaxf(tm1, fmaxf(s[nb][2], s[nb][3]));
        }
        tm0 = fmaxf(tm0, __shfl_xor_sync(0xffffffffu, tm0, 1));
        tm0 = fmaxf(tm0, __shfl_xor_sync(0xffffffffu, tm0, 2));
        tm1 = fmaxf(tm1, __shfl_xor_sync(0xffffffffu, tm1, 1));
        tm1 = fmaxf(tm1, __shfl_xor_sync(0xffffffffu, tm1, 2));

        float m0n = fmaxf(m0, tm0), m1n = fmaxf(m1, tm1);
        float corr0 = __expf(m0 - m0n), corr1 = __expf(m1 - m1n);
        m0 = m0n; m1 = m1n;
        l0 *= corr0; l1 *= corr1;

        #pragma unroll
        for (int nb = 0; nb < 8; nb++) {
            s[nb][0] = __expf(s[nb][0] - m0);
            s[nb][1] = __expf(s[nb][1] - m0);
            s[nb][2] = __expf(s[nb][2] - m1);
            s[nb][3] = __expf(s[nb][3] - m1);
            l0 += s[nb][0] + s[nb][1];
            l1 += s[nb][2] + s[nb][3];
            o[nb][0] *= corr0; o[nb][1] *= corr0;
            o[nb][2] *= corr1; o[nb][3] *= corr1;
        }

        // ---- P -> split-bf16 A-fragments ----
        uint32_t Ph[4][4], Pl[4][4];
        #pragma unroll
        for (int kb = 0; kb < 4; kb++) {
            #pragma unroll
            for (int q = 0; q < 4; q++) {
                int nb = kb * 2 + (q >> 1);
                float p0 = s[nb][(q & 1) * 2], p1 = s[nb][(q & 1) * 2 + 1];
                uint32_t ph = pkbf(p0, p1);
                Ph[kb][q] = ph;
                float pl0 = p0 - __uint_as_float(ph << 16);
                float pl1 = p1 - __uint_as_float(ph & 0xFFFF0000u);
                Pl[kb][q] = pkbf(pl0, pl1);
            }
        }

        // ---- O += P' V' ----
        #pragma unroll
        for (int kb = 0; kb < 12; kb++) {
            int krow = 64 + (kb & 3) * 16;
            int vcol = (kb < 8) ? 0 : 64;
            const uint32_t* af = (kb < 4) ? Ph[kb] : ((kb < 8) ? Pl[kb - 4] : Ph[kb - 8]);
            #pragma unroll
            for (int nbp = 0; nbp < 4; nbp++) {
                uint32_t r0, r1, r2, r3;
                uint32_t addr = smem_u32(&sm[(krow + (lane & 15)) * FROW
                                             + vcol + nbp * 16 + (lane >> 4) * 8]);
                ldsm_x4t(r0, r1, r2, r3, addr);
                mma16816(o[nbp * 2],     af, r0, r1);
                mma16816(o[nbp * 2 + 1], af, r2, r3);
            }
        }
        __syncthreads();   // before next tile overwrites smem
    }

    // ---- finalize: normalize + XSA correction ----
    l0 += __shfl_xor_sync(0xffffffffu, l0, 1);
    l0 += __shfl_xor_sync(0xffffffffu, l0, 2);
    l1 += __shfl_xor_sync(0xffffffffu, l1, 1);
    l1 += __shfl_xor_sync(0xffffffffu, l1, 2);
    float inv0 = 1.f / l0, inv1 = 1.f / l1;

    float2 vr0[8], vr1[8];
    float sov0 = 0.f, svv0 = 0.f, sov1 = 0.f, svv1 = 0.f;
    const float* vb = qkv + base + 2 * C_ + h * D_;
    #pragma unroll
    for (int nb = 0; nb < 8; nb++) {
        int d = nb * 8 + (lane & 3) * 2;
        vr0[nb] = *(const float2*)(vb + (size_t)qrow_g0 * C3_ + d);
        vr1[nb] = *(const float2*)(vb + (size_t)(qrow_g0 + 8) * C3_ + d);
        o[nb][0] *= inv0; o[nb][1] *= inv0; o[nb][2] *= inv1; o[nb][3] *= inv1;
        sov0 += o[nb][0] * vr0[nb].x + o[nb][1] * vr0[nb].y;
        svv0 += vr0[nb].x * vr0[nb].x + vr0[nb].y * vr0[nb].y;
        sov1 += o[nb][2] * vr1[nb].x + o[nb][3] * vr1[nb].y;
        svv1 += vr1[nb].x * vr1[nb].x + vr1[nb].y * vr1[nb].y;
    }
    sov0 += __shfl_xor_sync(0xffffffffu, sov0, 1);
    sov0 += __shfl_xor_sync(0xffffffffu, sov0, 2);
    svv0 += __shfl_xor_sync(0xffffffffu, svv0, 1);
    svv0 += __shfl_xor_sync(0xffffffffu, svv0, 2);
    sov1 += __shfl_xor_sync(0xffffffffu, sov1, 1);
    sov1 += __shfl_xor_sync(0xffffffffu, sov1, 2);
    svv1 += __shfl_xor_sync(0xffffffffu, svv1, 1);
    svv1 += __shfl_xor_sync(0xffffffffu, svv1, 2);

    float mx0 = fmaxf(sqrtf(svv0), 1e-12f);
    float mx1 = fmaxf(sqrtf(svv1), 1e-12f);
    float c0 = sov0 / (mx0 * mx0), c1 = sov1 / (mx1 * mx1);

    float* y0 = y + ((size_t)b * T_ + qrow_g0) * C_ + h * D_;
    float* y1 = y0 + 8 * C_;
    #pragma unroll
    for (int nb = 0; nb < 8; nb++) {
        int d = nb * 8 + (lane & 3) * 2;
        *(float2*)(y0 + d) = make_float2(o[nb][0] - c0 * vr0[nb].x, o[nb][1] - c0 * vr0[nb].y);
        *(float2*)(y1 + d) = make_float2(o[nb][2] - c1 * vr1[nb].x, o[nb][3] - c1 * vr1[nb].y);
    }
}

// ---------------------------------------------------------------------------
extern "C" void kernel_launch(void* const* d_in, const int* in_sizes, int n_in,
                              void* d_out, int out_size)
{
    const float* x  = (const float*)d_in[0];
    const float* Wa = (const float*)d_in[1];
    const float* ba = (const float*)d_in[2];
    const float* Wp = (const float*)d_in[3];
    const float* bp = (const float*)d_in[4];
    float* out = (float*)d_out;

    float *qkv, *yb;
    __nv_bfloat16 *A3, *B3;
    cudaGetSymbolAddress((void**)&qkv, g_qkv);
    cudaGetSymbolAddress((void**)&yb,  g_y);
    cudaGetSymbolAddress((void**)&A3,  g_A3);
    cudaGetSymbolAddress((void**)&B3,  g_B3);

    const int M = B_ * T_;

    prep_W<<<dim3(C3_ / 32, C_ / 32), 256>>>(Wa, B3, C3_);
    split_A<<<(M * C_) / 256, 256>>>(x, A3);
    hmma_gemm<<<dim3(C3_ / 128, M / 128), 256>>>(A3, B3, ba, qkv, M, C3_, K3_);

    sparsemax_k<<<(M * H_) / 4, 256>>>(qkv);

    flash_hmma<<<dim3(T_ / 128, H_, B_), 256>>>(qkv, yb);

    prep_W<<<dim3(C_ / 32, C_ / 32), 256>>>(Wp, B3, C_);
    split_A<<<(M * C_) / 256, 256>>>(yb, A3);
    hmma_gemm<<<dim3(C_ / 128, M / 128), 256>>>(A3, B3, bp, out, M, C_, K3_);
}

// round 6
// speedup vs baseline: 2.8809x; 1.1604x over previous
#include <cuda_runtime.h>
#include <cuda_bf16.h>
#include <math.h>
#include <stdint.h>

#define B_  4
#define T_  2048
#define C_  1024
#define H_  16
#define D_  64
#define C3_ 3072
#define K3_ 3072

typedef unsigned long long u64;

__device__ float g_qkv[(size_t)B_ * T_ * C3_];
__device__ float g_y[(size_t)B_ * T_ * C_];
__device__ __nv_bfloat16 g_A3[(size_t)B_ * T_ * K3_];
__device__ __nv_bfloat16 g_B3[(size_t)C3_ * K3_];

// ---- helpers ----
__device__ __forceinline__ uint32_t smem_u32(const void* p) {
    uint32_t a;
    asm("{ .reg .u64 t; cvta.to.shared.u64 t, %1; cvt.u32.u64 %0, t; }" : "=r"(a) : "l"(p));
    return a;
}
__device__ __forceinline__ void cp16(uint32_t dst, const void* src) {
    asm volatile("cp.async.cg.shared.global [%0], [%1], 16;" :: "r"(dst), "l"(src));
}
__device__ __forceinline__ void ldsm_x4(uint32_t& r0, uint32_t& r1, uint32_t& r2, uint32_t& r3,
                                        uint32_t addr) {
    asm volatile("ldmatrix.sync.aligned.m8n8.x4.shared.b16 {%0,%1,%2,%3},[%4];"
                 : "=r"(r0), "=r"(r1), "=r"(r2), "=r"(r3) : "r"(addr));
}
__device__ __forceinline__ void ldsm_x4t(uint32_t& r0, uint32_t& r1, uint32_t& r2, uint32_t& r3,
                                         uint32_t addr) {
    asm volatile("ldmatrix.sync.aligned.m8n8.x4.trans.shared.b16 {%0,%1,%2,%3},[%4];"
                 : "=r"(r0), "=r"(r1), "=r"(r2), "=r"(r3) : "r"(addr));
}
__device__ __forceinline__ void mma16816(float* c, const uint32_t* a, uint32_t b0, uint32_t b1) {
    asm volatile(
        "mma.sync.aligned.m16n8k16.row.col.f32.bf16.bf16.f32 "
        "{%0,%1,%2,%3},{%4,%5,%6,%7},{%8,%9},{%0,%1,%2,%3};"
        : "+f"(c[0]), "+f"(c[1]), "+f"(c[2]), "+f"(c[3])
        : "r"(a[0]), "r"(a[1]), "r"(a[2]), "r"(a[3]), "r"(b0), "r"(b1));
}
__device__ __forceinline__ uint32_t pkbf(float lo, float hi) {  // low half = lo
    uint32_t r; asm("cvt.rn.bf16x2.f32 %0,%1,%2;" : "=r"(r) : "f"(hi), "f"(lo)); return r;
}
// split float4 -> packed hi (2x bf16x2) and packed lo residual
__device__ __forceinline__ uint2 split4(float4 f, uint2& lo) {
    uint32_t h0 = pkbf(f.x, f.y);
    uint32_t h1 = pkbf(f.z, f.w);
    float l0 = f.x - __uint_as_float(h0 << 16);
    float l1 = f.y - __uint_as_float(h0 & 0xFFFF0000u);
    float l2 = f.z - __uint_as_float(h1 << 16);
    float l3 = f.w - __uint_as_float(h1 & 0xFFFF0000u);
    lo = make_uint2(pkbf(l0, l1), pkbf(l2, l3));
    return make_uint2(h0, h1);
}

// ---------------------------------------------------------------------------
// split_A (vectorized): src fp32 [M,1024] -> dst bf16 [M,3072] = [hi|lo|hi]
// ---------------------------------------------------------------------------
__global__ __launch_bounds__(256) void split_A(
    const float* __restrict__ src, __nv_bfloat16* __restrict__ dst)
{
    size_t idx = ((size_t)blockIdx.x * 256 + threadIdx.x) * 8;
    int m = (int)(idx >> 10), k = (int)(idx & 1023);
    float4 f0 = *(const float4*)(src + idx);
    float4 f1 = *(const float4*)(src + idx + 4);
    uint2 l0, l1;
    uint2 h0 = split4(f0, l0);
    uint2 h1 = split4(f1, l1);
    __nv_bfloat16* r = dst + (size_t)m * K3_;
    *(uint4*)(r + k)        = make_uint4(h0.x, h0.y, h1.x, h1.y);
    *(uint4*)(r + 1024 + k) = make_uint4(l0.x, l0.y, l1.x, l1.y);
    *(uint4*)(r + 2048 + k) = make_uint4(h0.x, h0.y, h1.x, h1.y);
}

// ---------------------------------------------------------------------------
// prep_W (vectorized writes): W fp32 [1024, N] -> Bo bf16 [N,3072] = [hi|hi|lo]
// ---------------------------------------------------------------------------
__global__ __launch_bounds__(256) void prep_W(
    const float* __restrict__ W, __nv_bfloat16* __restrict__ Bo, int N)
{
    __shared__ float t[32][33];
    int n0 = blockIdx.x * 32, k0 = blockIdx.y * 32;
    {
        int tx = threadIdx.x & 31, ty = threadIdx.x >> 5;
        #pragma unroll
        for (int i = 0; i < 4; i++)
            t[ty + i * 8][tx] = W[(size_t)(k0 + ty + i * 8) * N + n0 + tx];
    }
    __syncthreads();
    int kk = (threadIdx.x & 15) * 2, ny = threadIdx.x >> 4;
    #pragma unroll
    for (int i = 0; i < 2; i++) {
        int n = ny + i * 16;
        float wa = t[kk][n], wb = t[kk + 1][n];
        uint32_t hp = pkbf(wa, wb);
        float la = wa - __uint_as_float(hp << 16);
        float lb = wb - __uint_as_float(hp & 0xFFFF0000u);
        uint32_t lp = pkbf(la, lb);
        size_t r = (size_t)(n0 + n) * K3_;
        *(uint32_t*)(Bo + r + k0 + kk)        = hp;
        *(uint32_t*)(Bo + r + 1024 + k0 + kk) = hp;
        *(uint32_t*)(Bo + r + 2048 + k0 + kk) = lp;
    }
}

// ---------------------------------------------------------------------------
// HMMA GEMM (unchanged from r4/r5)
// ---------------------------------------------------------------------------
#define BK   32
#define ROWE 40

__global__ __launch_bounds__(256) void hmma_gemm(
    const __nv_bfloat16* __restrict__ A, const __nv_bfloat16* __restrict__ Bk,
    const float* __restrict__ bias, float* __restrict__ Cout,
    int M, int N, int K)
{
    __shared__ __nv_bfloat16 sA[2][128 * ROWE];
    __shared__ __nv_bfloat16 sB[2][128 * ROWE];

    const int tid  = threadIdx.x;
    const int lane = tid & 31;
    const int wid  = tid >> 5;
    const int wm   = wid >> 2;
    const int wn   = wid & 3;
    const int m0 = blockIdx.y * 128, n0 = blockIdx.x * 128;

    const uint32_t sA_b = smem_u32(&sA[0][0]);
    const uint32_t sB_b = smem_u32(&sB[0][0]);
    const uint32_t bufbytes = 128 * ROWE * 2;

    auto load_tile = [&](int buf, int kt) {
        const __nv_bfloat16* Ag = A + (size_t)m0 * K + kt * BK;
        const __nv_bfloat16* Bg = Bk + (size_t)n0 * K + kt * BK;
        #pragma unroll
        for (int it = 0; it < 2; it++) {
            int c = tid + it * 256;
            int row = c >> 2, seg = c & 3;
            uint32_t doff = (uint32_t)(row * ROWE + seg * 8) * 2;
            cp16(sA_b + buf * bufbytes + doff, Ag + (size_t)row * K + seg * 8);
            cp16(sB_b + buf * bufbytes + doff, Bg + (size_t)row * K + seg * 8);
        }
        asm volatile("cp.async.commit_group;" ::: "memory");
    };

    float acc[4][4][4];
    #pragma unroll
    for (int i = 0; i < 4; i++)
        #pragma unroll
        for (int j = 0; j < 4; j++)
            #pragma unroll
            for (int e = 0; e < 4; e++) acc[i][j][e] = 0.f;

    const int nkt = K / BK;
    load_tile(0, 0);

    const int a_row = wm * 64 + (lane & 15);
    const int a_ko  = (lane >> 4) * 8;
    const int b_row = wn * 32 + (lane & 7) + ((lane >> 4) & 1) * 8;
    const int b_ko  = ((lane >> 3) & 1) * 8;

    for (int kt = 0; kt < nkt; kt++) {
        if (kt + 1 < nkt) load_tile((kt + 1) & 1, kt + 1);
        else asm volatile("cp.async.commit_group;" ::: "memory");
        asm volatile("cp.async.wait_group 1;" ::: "memory");
        __syncthreads();

        const uint32_t aT = sA_b + (kt & 1) * bufbytes;
        const uint32_t bT = sB_b + (kt & 1) * bufbytes;

        #pragma unroll
        for (int ks = 0; ks < 2; ks++) {
            uint32_t af[4][4];
            #pragma unroll
            for (int mi = 0; mi < 4; mi++)
                ldsm_x4(af[mi][0], af[mi][1], af[mi][2], af[mi][3],
                        aT + (uint32_t)((a_row + mi * 16) * ROWE + ks * 16 + a_ko) * 2);
            uint32_t bf[4][2];
            #pragma unroll
            for (int nb = 0; nb < 2; nb++) {
                uint32_t r0, r1, r2, r3;
                ldsm_x4(r0, r1, r2, r3,
                        bT + (uint32_t)((b_row + nb * 16) * ROWE + ks * 16 + b_ko) * 2);
                bf[nb * 2][0] = r0; bf[nb * 2][1] = r1;
                bf[nb * 2 + 1][0] = r2; bf[nb * 2 + 1][1] = r3;
            }
            #pragma unroll
            for (int mi = 0; mi < 4; mi++)
                #pragma unroll
                for (int ni = 0; ni < 4; ni++)
                    mma16816(acc[mi][ni], af[mi], bf[ni][0], bf[ni][1]);
        }
        __syncthreads();
    }

    #pragma unroll
    for (int mi = 0; mi < 4; mi++) {
        int row_g = m0 + wm * 64 + mi * 16 + (lane >> 2);
        #pragma unroll
        for (int ni = 0; ni < 4; ni++) {
            int col_g = n0 + wn * 32 + ni * 8 + (lane & 3) * 2;
            float b0 = bias[col_g], b1 = bias[col_g + 1];
            float2 o0 = make_float2(acc[mi][ni][0] + b0, acc[mi][ni][1] + b1);
            float2 o1 = make_float2(acc[mi][ni][2] + b0, acc[mi][ni][3] + b1);
            *(float2*)(Cout + (size_t)row_g * N + col_g) = o0;
            *(float2*)(Cout + (size_t)(row_g + 8) * N + col_g) = o1;
        }
    }
}

// ---------------------------------------------------------------------------
// Sparsemax: one WARP per row, bitonic sort of 64 vals (32 lanes x 2 regs),
// shuffle prefix-scan, closed-form tau. O(d log^2 d) instead of O(d^2).
// ---------------------------------------------------------------------------
__global__ __launch_bounds__(256) void sparsemax_k(float* __restrict__ qkv)
{
    const int lane = threadIdx.x & 31;
    const int wrp  = threadIdx.x >> 5;
    const size_t row = (size_t)blockIdx.x * 8 + wrp;
    const size_t bt  = row >> 4;
    const int    h   = (int)(row & 15);

    float* p = qkv + bt * C3_ + C_ + h * D_;
    float z0 = p[lane], z1 = p[lane + 32];
    float v0 = z0, v1 = z1;          // idx(v0)=lane, idx(v1)=lane+32

    // bitonic sort, descending over idx order
    #pragma unroll
    for (int k = 2; k <= 64; k <<= 1) {
        #pragma unroll
        for (int j = k >> 1; j > 0; j >>= 1) {
            if (j < 32) {
                float p0 = __shfl_xor_sync(0xffffffffu, v0, j);
                float p1 = __shfl_xor_sync(0xffffffffu, v1, j);
                bool lower = (lane & j) == 0;
                bool up0 = (lane & k) != 0;
                bool up1 = ((lane + 32) & k) != 0;
                v0 = (lower == up0) ? fminf(v0, p0) : fmaxf(v0, p0);
                v1 = (lower == up1) ? fminf(v1, p1) : fmaxf(v1, p1);
            } else {   // j==32 (k==64): in-thread pair, descending merge
                float a = fmaxf(v0, v1), bmin = fminf(v0, v1);
                v0 = a; v1 = bmin;
            }
        }
    }

    // inclusive prefix scan of sorted values
    float c0 = v0;
    #pragma unroll
    for (int o = 1; o < 32; o <<= 1) {
        float t = __shfl_up_sync(0xffffffffu, c0, o);
        if (lane >= o) c0 += t;
    }
    float c1 = v1;
    #pragma unroll
    for (int o = 1; o < 32; o <<= 1) {
        float t = __shfl_up_sync(0xffffffffu, c1, o);
        if (lane >= o) c1 += t;
    }
    c1 += __shfl_sync(0xffffffffu, c0, 31);

    bool s0 = 1.f + (float)(lane + 1)  * v0 > c0;
    bool s1 = 1.f + (float)(lane + 33) * v1 > c1;
    int rho = __popc(__ballot_sync(0xffffffffu, s0)) +
              __popc(__ballot_sync(0xffffffffu, s1));
    int ridx = rho - 1;
    float csA = __shfl_sync(0xffffffffu, c0, ridx & 31);
    float csB = __shfl_sync(0xffffffffu, c1, ridx & 31);
    float cs  = (ridx < 32) ? csA : csB;
    float tau = (cs - 1.f) / (float)rho;

    p[lane]      = fmaxf(z0 - tau, 0.f);
    p[lane + 32] = fmaxf(z1 - tau, 0.f);
}

// ---------------------------------------------------------------------------
// Flash attention on tensor cores + fused XSA (packed split conversions).
// ---------------------------------------------------------------------------
#define FROW 136

__global__ __launch_bounds__(256) void flash_hmma(
    const float* __restrict__ qkv, float* __restrict__ y)
{
    __shared__ __align__(16) __nv_bfloat16 sm[128 * FROW];

    const int tid  = threadIdx.x;
    const int lane = tid & 31;
    const int w    = tid >> 5;
    const int qt = blockIdx.x, h = blockIdx.y, b = blockIdx.z;
    const size_t base = (size_t)b * T_ * C3_;

    // ---- stage Q (scaled) as [hi|lo], packed stores ----
    for (int i = tid; i < 2048; i += 256) {
        int row = i >> 4, d = (i & 15) * 4;
        float4 f4 = *(const float4*)(qkv + base + (size_t)(qt * 128 + row) * C3_ + h * D_ + d);
        f4.x *= 0.125f; f4.y *= 0.125f; f4.z *= 0.125f; f4.w *= 0.125f;
        uint2 lo; uint2 hi = split4(f4, lo);
        *(uint2*)&sm[row * FROW + d]      = hi;
        *(uint2*)&sm[row * FROW + 64 + d] = lo;
    }
    __syncthreads();

    uint32_t qf[8][4];
    #pragma unroll
    for (int kb = 0; kb < 8; kb++) {
        uint32_t addr = smem_u32(&sm[(w * 16 + (lane & 15)) * FROW + kb * 16 + (lane >> 4) * 8]);
        ldsm_x4(qf[kb][0], qf[kb][1], qf[kb][2], qf[kb][3], addr);
    }
    __syncthreads();

    float o[8][4];
    #pragma unroll
    for (int nb = 0; nb < 8; nb++)
        #pragma unroll
        for (int e = 0; e < 4; e++) o[nb][e] = 0.f;
    float m0 = -1e30f, m1 = -1e30f, l0 = 0.f, l1 = 0.f;

    const int qrow_g0 = qt * 128 + w * 16 + (lane >> 2);
    const int nkt = (qt + 1) * 2;

    for (int kt = 0; kt < nkt; kt++) {
        // ---- load + split K (rows 0..63) and V (rows 64..127), packed ----
        for (int i = tid; i < 1024; i += 256) {
            int row = i >> 4, d = (i & 15) * 4;
            const float* kp = qkv + base + (size_t)(kt * 64 + row) * C3_ + C_ + h * D_ + d;
            float4 k4 = *(const float4*)kp;
            float4 v4 = *(const float4*)(kp + C_);
            uint2 klo; uint2 khi = split4(k4, klo);
            uint2 vlo; uint2 vhi = split4(v4, vlo);
            *(uint2*)&sm[row * FROW + d]              = khi;
            *(uint2*)&sm[row * FROW + 64 + d]         = klo;
            *(uint2*)&sm[(64 + row) * FROW + d]       = vhi;
            *(uint2*)&sm[(64 + row) * FROW + 64 + d]  = vlo;
        }
        __syncthreads();

        // ---- S = Q' K'^T ----
        float s[8][4];
        #pragma unroll
        for (int nb = 0; nb < 8; nb++)
            #pragma unroll
            for (int e = 0; e < 4; e++) s[nb][e] = 0.f;

        #pragma unroll
        for (int kb = 0; kb < 12; kb++) {
            int bcol = (kb < 4) ? kb * 16 : ((kb < 8) ? (kb - 4) * 16 : 64 + (kb - 8) * 16);
            const uint32_t* af = (kb < 8) ? qf[kb] : qf[kb - 8];
            #pragma unroll
            for (int nbp = 0; nbp < 4; nbp++) {
                uint32_t r0, r1, r2, r3;
                uint32_t addr = smem_u32(&sm[(nbp * 16 + (lane & 7) + ((lane >> 4) & 1) * 8) * FROW
                                             + bcol + ((lane >> 3) & 1) * 8]);
                ldsm_x4(r0, r1, r2, r3, addr);
                mma16816(s[nbp * 2],     af, r0, r1);
                mma16816(s[nbp * 2 + 1], af, r2, r3);
            }
        }

        // ---- causal mask ----
        if (kt * 64 + 63 > qt * 128 + w * 16) {
            #pragma unroll
            for (int nb = 0; nb < 8; nb++) {
                int col = kt * 64 + nb * 8 + (lane & 3) * 2;
                if (col     > qrow_g0)     s[nb][0] = -1e30f;
                if (col + 1 > qrow_g0)     s[nb][1] = -1e30f;
                if (col     > qrow_g0 + 8) s[nb][2] = -1e30f;
                if (col + 1 > qrow_g0 + 8) s[nb][3] = -1e30f;
            }
        }

        // ---- online softmax ----
        float tm0 = -1e30f, tm1 = -1e30f;
        #pragma unroll
        for (int nb = 0; nb < 8; nb++) {
            tm0 = fmaxf(tm0, fmaxf(s[nb][0], s[nb][1]));
            tm1 = fmaxf(tm1, fmaxf(s[nb][2], s[nb][3]));
        }
        tm0 = fmaxf(tm0, __shfl_xor_sync(0xffffffffu, tm0, 1));
        tm0 = fmaxf(tm0, __shfl_xor_sync(0xffffffffu, tm0, 2));
        tm1 = fmaxf(tm1, __shfl_xor_sync(0xffffffffu, tm1, 1));
        tm1 = fmaxf(tm1, __shfl_xor_sync(0xffffffffu, tm1, 2));

        float m0n = fmaxf(m0, tm0), m1n = fmaxf(m1, tm1);
        float corr0 = __expf(m0 - m0n), corr1 = __expf(m1 - m1n);
        m0 = m0n; m1 = m1n;
        l0 *= corr0; l1 *= corr1;

        #pragma unroll
        for (int nb = 0; nb < 8; nb++) {
            s[nb][0] = __expf(s[nb][0] - m0);
            s[nb][1] = __expf(s[nb][1] - m0);
            s[nb][2] = __expf(s[nb][2] - m1);
            s[nb][3] = __expf(s[nb][3] - m1);
            l0 += s[nb][0] + s[nb][1];
            l1 += s[nb][2] + s[nb][3];
            o[nb][0] *= corr0; o[nb][1] *= corr0;
            o[nb][2] *= corr1; o[nb][3] *= corr1;
        }

        // ---- P -> split-bf16 A-fragments ----
        uint32_t Ph[4][4], Pl[4][4];
        #pragma unroll
        for (int kb = 0; kb < 4; kb++) {
            #pragma unroll
            for (int q = 0; q < 4; q++) {
                int nb = kb * 2 + (q >> 1);
                float p0 = s[nb][(q & 1) * 2], p1 = s[nb][(q & 1) * 2 + 1];
                uint32_t ph = pkbf(p0, p1);
                Ph[kb][q] = ph;
                float pl0 = p0 - __uint_as_float(ph << 16);
                float pl1 = p1 - __uint_as_float(ph & 0xFFFF0000u);
                Pl[kb][q] = pkbf(pl0, pl1);
            }
        }

        // ---- O += P' V' ----
        #pragma unroll
        for (int kb = 0; kb < 12; kb++) {
            int krow = 64 + (kb & 3) * 16;
            int vcol = (kb < 8) ? 0 : 64;
            const uint32_t* af = (kb < 4) ? Ph[kb] : ((kb < 8) ? Pl[kb - 4] : Ph[kb - 8]);
            #pragma unroll
            for (int nbp = 0; nbp < 4; nbp++) {
                uint32_t r0, r1, r2, r3;
                uint32_t addr = smem_u32(&sm[(krow + (lane & 15)) * FROW
                                             + vcol + nbp * 16 + (lane >> 4) * 8]);
                ldsm_x4t(r0, r1, r2, r3, addr);
                mma16816(o[nbp * 2],     af, r0, r1);
                mma16816(o[nbp * 2 + 1], af, r2, r3);
            }
        }
        __syncthreads();
    }

    // ---- finalize: normalize + XSA correction ----
    l0 += __shfl_xor_sync(0xffffffffu, l0, 1);
    l0 += __shfl_xor_sync(0xffffffffu, l0, 2);
    l1 += __shfl_xor_sync(0xffffffffu, l1, 1);
    l1 += __shfl_xor_sync(0xffffffffu, l1, 2);
    float inv0 = 1.f / l0, inv1 = 1.f / l1;

    float2 vr0[8], vr1[8];
    float sov0 = 0.f, svv0 = 0.f, sov1 = 0.f, svv1 = 0.f;
    const float* vb = qkv + base + 2 * C_ + h * D_;
    #pragma unroll
    for (int nb = 0; nb < 8; nb++) {
        int d = nb * 8 + (lane & 3) * 2;
        vr0[nb] = *(const float2*)(vb + (size_t)qrow_g0 * C3_ + d);
        vr1[nb] = *(const float2*)(vb + (size_t)(qrow_g0 + 8) * C3_ + d);
        o[nb][0] *= inv0; o[nb][1] *= inv0; o[nb][2] *= inv1; o[nb][3] *= inv1;
        sov0 += o[nb][0] * vr0[nb].x + o[nb][1] * vr0[nb].y;
        svv0 += vr0[nb].x * vr0[nb].x + vr0[nb].y * vr0[nb].y;
        sov1 += o[nb][2] * vr1[nb].x + o[nb][3] * vr1[nb].y;
        svv1 += vr1[nb].x * vr1[nb].x + vr1[nb].y * vr1[nb].y;
    }
    sov0 += __shfl_xor_sync(0xffffffffu, sov0, 1);
    sov0 += __shfl_xor_sync(0xffffffffu, sov0, 2);
    svv0 += __shfl_xor_sync(0xffffffffu, svv0, 1);
    svv0 += __shfl_xor_sync(0xffffffffu, svv0, 2);
    sov1 += __shfl_xor_sync(0xffffffffu, sov1, 1);
    sov1 += __shfl_xor_sync(0xffffffffu, sov1, 2);
    svv1 += __shfl_xor_sync(0xffffffffu, svv1, 1);
    svv1 += __shfl_xor_sync(0xffffffffu, svv1, 2);

    float mx0 = fmaxf(sqrtf(svv0), 1e-12f);
    float mx1 = fmaxf(sqrtf(svv1), 1e-12f);
    float c0 = sov0 / (mx0 * mx0), c1 = sov1 / (mx1 * mx1);

    float* y0 = y + ((size_t)b * T_ + qrow_g0) * C_ + h * D_;
    float* y1 = y0 + 8 * C_;
    #pragma unroll
    for (int nb = 0; nb < 8; nb++) {
        int d = nb * 8 + (lane & 3) * 2;
        *(float2*)(y0 + d) = make_float2(o[nb][0] - c0 * vr0[nb].x, o[nb][1] - c0 * vr0[nb].y);
        *(float2*)(y1 + d) = make_float2(o[nb][2] - c1 * vr1[nb].x, o[nb][3] - c1 * vr1[nb].y);
    }
}

// ---------------------------------------------------------------------------
extern "C" void kernel_launch(void* const* d_in, const int* in_sizes, int n_in,
                              void* d_out, int out_size)
{
    const float* x  = (const float*)d_in[0];
    const float* Wa = (const float*)d_in[1];
    const float* ba = (const float*)d_in[2];
    const float* Wp = (const float*)d_in[3];
    const float* bp = (const float*)d_in[4];
    float* out = (float*)d_out;

    float *qkv, *yb;
    __nv_bfloat16 *A3, *B3;
    cudaGetSymbolAddress((void**)&qkv, g_qkv);
    cudaGetSymbolAddress((void**)&yb,  g_y);
    cudaGetSymbolAddress((void**)&A3,  g_A3);
    cudaGetSymbolAddress((void**)&B3,  g_B3);

    const int M = B_ * T_;

    prep_W<<<dim3(C3_ / 32, C_ / 32), 256>>>(Wa, B3, C3_);
    split_A<<<(M * C_) / (256 * 8), 256>>>(x, A3);
    hmma_gemm<<<dim3(C3_ / 128, M / 128), 256>>>(A3, B3, ba, qkv, M, C3_, K3_);

    sparsemax_k<<<(M * H_) / 8, 256>>>(qkv);

    flash_hmma<<<dim3(T_ / 128, H_, B_), 256>>>(qkv, yb);

    prep_W<<<dim3(C_ / 32, C_ / 32), 256>>>(Wp, B3, C_);
    split_A<<<(M * C_) / (256 * 8), 256>>>(yb, A3);
    hmma_gemm<<<dim3(C_ / 128, M / 128), 256>>>(A3, B3, bp, out, M, C_, K3_);
}

// round 7
// speedup vs baseline: 3.4461x; 1.1962x over previous
#include <cuda_runtime.h>
#include <cuda_bf16.h>
#include <math.h>
#include <stdint.h>

#define B_  4
#define T_  2048
#define C_  1024
#define H_  16
#define D_  64
#define C3_ 3072
#define K3_ 3072

typedef unsigned long long u64;

__device__ float g_qkv[(size_t)B_ * T_ * C3_];
__device__ __nv_bfloat16 g_A3[(size_t)B_ * T_ * K3_];
__device__ __nv_bfloat16 g_B3[(size_t)C3_ * K3_];
__device__ __nv_bfloat16 g_K[(size_t)B_ * H_ * T_ * 128];   // [b,h,t][hi64|lo64]
__device__ __nv_bfloat16 g_V[(size_t)B_ * H_ * T_ * 128];

// ---- helpers ----
__device__ __forceinline__ uint32_t smem_u32(const void* p) {
    uint32_t a;
    asm("{ .reg .u64 t; cvta.to.shared.u64 t, %1; cvt.u32.u64 %0, t; }" : "=r"(a) : "l"(p));
    return a;
}
__device__ __forceinline__ void cp16(uint32_t dst, const void* src) {
    asm volatile("cp.async.cg.shared.global [%0], [%1], 16;" :: "r"(dst), "l"(src));
}
__device__ __forceinline__ void ldsm_x4(uint32_t& r0, uint32_t& r1, uint32_t& r2, uint32_t& r3,
                                        uint32_t addr) {
    asm volatile("ldmatrix.sync.aligned.m8n8.x4.shared.b16 {%0,%1,%2,%3},[%4];"
                 : "=r"(r0), "=r"(r1), "=r"(r2), "=r"(r3) : "r"(addr));
}
__device__ __forceinline__ void ldsm_x4t(uint32_t& r0, uint32_t& r1, uint32_t& r2, uint32_t& r3,
                                         uint32_t addr) {
    asm volatile("ldmatrix.sync.aligned.m8n8.x4.trans.shared.b16 {%0,%1,%2,%3},[%4];"
                 : "=r"(r0), "=r"(r1), "=r"(r2), "=r"(r3) : "r"(addr));
}
__device__ __forceinline__ void mma16816(float* c, const uint32_t* a, uint32_t b0, uint32_t b1) {
    asm volatile(
        "mma.sync.aligned.m16n8k16.row.col.f32.bf16.bf16.f32 "
        "{%0,%1,%2,%3},{%4,%5,%6,%7},{%8,%9},{%0,%1,%2,%3};"
        : "+f"(c[0]), "+f"(c[1]), "+f"(c[2]), "+f"(c[3])
        : "r"(a[0]), "r"(a[1]), "r"(a[2]), "r"(a[3]), "r"(b0), "r"(b1));
}
__device__ __forceinline__ uint32_t pkbf(float lo, float hi) {
    uint32_t r; asm("cvt.rn.bf16x2.f32 %0,%1,%2;" : "=r"(r) : "f"(hi), "f"(lo)); return r;
}
__device__ __forceinline__ uint32_t split2(float a, float b, uint32_t& lo) {
    uint32_t hp = pkbf(a, b);
    float la = a - __uint_as_float(hp << 16);
    float lb = b - __uint_as_float(hp & 0xFFFF0000u);
    lo = pkbf(la, lb);
    return hp;
}
__device__ __forceinline__ uint2 split4(float4 f, uint2& lo) {
    uint32_t l0, l1;
    uint32_t h0 = split2(f.x, f.y, l0);
    uint32_t h1 = split2(f.z, f.w, l1);
    lo = make_uint2(l0, l1);
    return make_uint2(h0, h1);
}

// ---------------------------------------------------------------------------
// split_A: src fp32 [M,1024] -> dst bf16 [M,3072] = [hi|lo|hi]
// ---------------------------------------------------------------------------
__global__ __launch_bounds__(256) void split_A(
    const float* __restrict__ src, __nv_bfloat16* __restrict__ dst)
{
    size_t idx = ((size_t)blockIdx.x * 256 + threadIdx.x) * 8;
    int m = (int)(idx >> 10), k = (int)(idx & 1023);
    float4 f0 = *(const float4*)(src + idx);
    float4 f1 = *(const float4*)(src + idx + 4);
    uint2 l0, l1;
    uint2 h0 = split4(f0, l0);
    uint2 h1 = split4(f1, l1);
    __nv_bfloat16* r = dst + (size_t)m * K3_;
    *(uint4*)(r + k)        = make_uint4(h0.x, h0.y, h1.x, h1.y);
    *(uint4*)(r + 1024 + k) = make_uint4(l0.x, l0.y, l1.x, l1.y);
    *(uint4*)(r + 2048 + k) = make_uint4(h0.x, h0.y, h1.x, h1.y);
}

// ---------------------------------------------------------------------------
// prep_W: W fp32 [1024, N] -> Bo bf16 [N,3072] = [hi|hi|lo]
// ---------------------------------------------------------------------------
__global__ __launch_bounds__(256) void prep_W(
    const float* __restrict__ W, __nv_bfloat16* __restrict__ Bo, int N)
{
    __shared__ float t[32][33];
    int n0 = blockIdx.x * 32, k0 = blockIdx.y * 32;
    {
        int tx = threadIdx.x & 31, ty = threadIdx.x >> 5;
        #pragma unroll
        for (int i = 0; i < 4; i++)
            t[ty + i * 8][tx] = W[(size_t)(k0 + ty + i * 8) * N + n0 + tx];
    }
    __syncthreads();
    int kk = (threadIdx.x & 15) * 2, ny = threadIdx.x >> 4;
    #pragma unroll
    for (int i = 0; i < 2; i++) {
        int n = ny + i * 16;
        uint32_t lp;
        uint32_t hp = split2(t[kk][n], t[kk + 1][n], lp);
        size_t r = (size_t)(n0 + n) * K3_;
        *(uint32_t*)(Bo + r + k0 + kk)        = hp;
        *(uint32_t*)(Bo + r + 1024 + k0 + kk) = hp;
        *(uint32_t*)(Bo + r + 2048 + k0 + kk) = lp;
    }
}

// ---------------------------------------------------------------------------
// HMMA GEMM (unchanged)
// ---------------------------------------------------------------------------
#define BK   32
#define ROWE 40

__global__ __launch_bounds__(256) void hmma_gemm(
    const __nv_bfloat16* __restrict__ A, const __nv_bfloat16* __restrict__ Bk,
    const float* __restrict__ bias, float* __restrict__ Cout,
    int M, int N, int K)
{
    __shared__ __nv_bfloat16 sA[2][128 * ROWE];
    __shared__ __nv_bfloat16 sB[2][128 * ROWE];

    const int tid  = threadIdx.x;
    const int lane = tid & 31;
    const int wid  = tid >> 5;
    const int wm   = wid >> 2;
    const int wn   = wid & 3;
    const int m0 = blockIdx.y * 128, n0 = blockIdx.x * 128;

    const uint32_t sA_b = smem_u32(&sA[0][0]);
    const uint32_t sB_b = smem_u32(&sB[0][0]);
    const uint32_t bufbytes = 128 * ROWE * 2;

    auto load_tile = [&](int buf, int kt) {
        const __nv_bfloat16* Ag = A + (size_t)m0 * K + kt * BK;
        const __nv_bfloat16* Bg = Bk + (size_t)n0 * K + kt * BK;
        #pragma unroll
        for (int it = 0; it < 2; it++) {
            int c = tid + it * 256;
            int row = c >> 2, seg = c & 3;
            uint32_t doff = (uint32_t)(row * ROWE + seg * 8) * 2;
            cp16(sA_b + buf * bufbytes + doff, Ag + (size_t)row * K + seg * 8);
            cp16(sB_b + buf * bufbytes + doff, Bg + (size_t)row * K + seg * 8);
        }
        asm volatile("cp.async.commit_group;" ::: "memory");
    };

    float acc[4][4][4];
    #pragma unroll
    for (int i = 0; i < 4; i++)
        #pragma unroll
        for (int j = 0; j < 4; j++)
            #pragma unroll
            for (int e = 0; e < 4; e++) acc[i][j][e] = 0.f;

    const int nkt = K / BK;
    load_tile(0, 0);

    const int a_row = wm * 64 + (lane & 15);
    const int a_ko  = (lane >> 4) * 8;
    const int b_row = wn * 32 + (lane & 7) + ((lane >> 4) & 1) * 8;
    const int b_ko  = ((lane >> 3) & 1) * 8;

    for (int kt = 0; kt < nkt; kt++) {
        if (kt + 1 < nkt) load_tile((kt + 1) & 1, kt + 1);
        else asm volatile("cp.async.commit_group;" ::: "memory");
        asm volatile("cp.async.wait_group 1;" ::: "memory");
        __syncthreads();

        const uint32_t aT = sA_b + (kt & 1) * bufbytes;
        const uint32_t bT = sB_b + (kt & 1) * bufbytes;

        #pragma unroll
        for (int ks = 0; ks < 2; ks++) {
            uint32_t af[4][4];
            #pragma unroll
            for (int mi = 0; mi < 4; mi++)
                ldsm_x4(af[mi][0], af[mi][1], af[mi][2], af[mi][3],
                        aT + (uint32_t)((a_row + mi * 16) * ROWE + ks * 16 + a_ko) * 2);
            uint32_t bf[4][2];
            #pragma unroll
            for (int nb = 0; nb < 2; nb++) {
                uint32_t r0, r1, r2, r3;
                ldsm_x4(r0, r1, r2, r3,
                        bT + (uint32_t)((b_row + nb * 16) * ROWE + ks * 16 + b_ko) * 2);
                bf[nb * 2][0] = r0; bf[nb * 2][1] = r1;
                bf[nb * 2 + 1][0] = r2; bf[nb * 2 + 1][1] = r3;
            }
            #pragma unroll
            for (int mi = 0; mi < 4; mi++)
                #pragma unroll
                for (int ni = 0; ni < 4; ni++)
                    mma16816(acc[mi][ni], af[mi], bf[ni][0], bf[ni][1]);
        }
        __syncthreads();
    }

    #pragma unroll
    for (int mi = 0; mi < 4; mi++) {
        int row_g = m0 + wm * 64 + mi * 16 + (lane >> 2);
        #pragma unroll
        for (int ni = 0; ni < 4; ni++) {
            int col_g = n0 + wn * 32 + ni * 8 + (lane & 3) * 2;
            float b0 = bias[col_g], b1 = bias[col_g + 1];
            float2 o0 = make_float2(acc[mi][ni][0] + b0, acc[mi][ni][1] + b1);
            float2 o1 = make_float2(acc[mi][ni][2] + b0, acc[mi][ni][3] + b1);
            *(float2*)(Cout + (size_t)row_g * N + col_g) = o0;
            *(float2*)(Cout + (size_t)(row_g + 8) * N + col_g) = o1;
        }
    }
}

// ---------------------------------------------------------------------------
// Sparsemax over K head-dim + fused split of K AND V into bf16 [hi|lo] rows.
// One warp per (b,t,h) row; lane holds elements (2*lane, 2*lane+1).
// ---------------------------------------------------------------------------
__global__ __launch_bounds__(256) void sparsemax_kv(
    const float* __restrict__ qkv,
    __nv_bfloat16* __restrict__ Ko, __nv_bfloat16* __restrict__ Vo)
{
    const int lane = threadIdx.x & 31;
    const int wrp  = threadIdx.x >> 5;
    const size_t row = (size_t)blockIdx.x * 8 + wrp;
    const size_t bt  = row >> 4;                 // b*T + t
    const int    h   = (int)(row & 15);
    const int    b   = (int)(bt >> 11);
    const int    t   = (int)(bt & 2047);

    const float* pk = qkv + bt * C3_ + C_ + h * D_;
    float2 z = *(const float2*)(pk + 2 * lane);
    float v0 = z.x, v1 = z.y;          // arbitrary initial positions: sort net handles it

    #pragma unroll
    for (int k = 2; k <= 64; k <<= 1) {
        #pragma unroll
        for (int j = k >> 1; j > 0; j >>= 1) {
            if (j < 32) {
                float p0 = __shfl_xor_sync(0xffffffffu, v0, j);
                float p1 = __shfl_xor_sync(0xffffffffu, v1, j);
                bool lower = (lane & j) == 0;
                bool up0 = (lane & k) != 0;
                bool up1 = ((lane + 32) & k) != 0;
                v0 = (lower == up0) ? fminf(v0, p0) : fmaxf(v0, p0);
                v1 = (lower == up1) ? fminf(v1, p1) : fmaxf(v1, p1);
            } else {
                float a = fmaxf(v0, v1), bmin = fminf(v0, v1);
                v0 = a; v1 = bmin;
            }
        }
    }

    float c0 = v0;
    #pragma unroll
    for (int o = 1; o < 32; o <<= 1) {
        float tt = __shfl_up_sync(0xffffffffu, c0, o);
        if (lane >= o) c0 += tt;
    }
    float c1 = v1;
    #pragma unroll
    for (int o = 1; o < 32; o <<= 1) {
        float tt = __shfl_up_sync(0xffffffffu, c1, o);
        if (lane >= o) c1 += tt;
    }
    c1 += __shfl_sync(0xffffffffu, c0, 31);

    bool s0 = 1.f + (float)(lane + 1)  * v0 > c0;
    bool s1 = 1.f + (float)(lane + 33) * v1 > c1;
    int rho = __popc(__ballot_sync(0xffffffffu, s0)) +
              __popc(__ballot_sync(0xffffffffu, s1));
    int ridx = rho - 1;
    float csA = __shfl_sync(0xffffffffu, c0, ridx & 31);
    float csB = __shfl_sync(0xffffffffu, c1, ridx & 31);
    float cs  = (ridx < 32) ? csA : csB;
    float tau = (cs - 1.f) / (float)rho;

    // split K result
    float k0 = fmaxf(z.x - tau, 0.f), k1 = fmaxf(z.y - tau, 0.f);
    uint32_t klo; uint32_t khi = split2(k0, k1, klo);
    __nv_bfloat16* kr = Ko + ((size_t)(b * H_ + h) * T_ + t) * 128;
    *(uint32_t*)(kr + 2 * lane)      = khi;
    *(uint32_t*)(kr + 64 + 2 * lane) = klo;

    // split V row too
    float2 vv = *(const float2*)(pk + C_ + 2 * lane);
    uint32_t vlo; uint32_t vhi = split2(vv.x, vv.y, vlo);
    __nv_bfloat16* vr = Vo + ((size_t)(b * H_ + h) * T_ + t) * 128;
    *(uint32_t*)(vr + 2 * lane)      = vhi;
    *(uint32_t*)(vr + 64 + 2 * lane) = vlo;
}

// ---------------------------------------------------------------------------
// Flash attention, cp.async double-buffered pre-split K/V, fused XSA,
// epilogue writes y directly in split-A3 [hi|lo|hi] layout.
// ---------------------------------------------------------------------------
#define FROW 136
#define FBUF (128 * FROW)

__global__ __launch_bounds__(256) void flash_hmma(
    const float* __restrict__ qkv,
    const __nv_bfloat16* __restrict__ Ks, const __nv_bfloat16* __restrict__ Vs,
    __nv_bfloat16* __restrict__ A3out)
{
    extern __shared__ __align__(16) __nv_bfloat16 smx[];   // 2 buffers of FBUF

    const int tid  = threadIdx.x;
    const int lane = tid & 31;
    const int w    = tid >> 5;
    const int qt = blockIdx.x, h = blockIdx.y, b = blockIdx.z;
    const size_t base = (size_t)b * T_ * C3_;

    const __nv_bfloat16* Kb = Ks + (size_t)(b * H_ + h) * T_ * 128;
    const __nv_bfloat16* Vb = Vs + (size_t)(b * H_ + h) * T_ * 128;
    const uint32_t smb0 = smem_u32(smx);

    auto load_tile = [&](int buf, int kt) {
        const __nv_bfloat16* kg = Kb + (size_t)kt * 64 * 128;
        const __nv_bfloat16* vg = Vb + (size_t)kt * 64 * 128;
        uint32_t sb = smb0 + buf * (FBUF * 2);
        #pragma unroll
        for (int it = 0; it < 4; it++) {
            int c = tid + it * 256;
            int j = c >> 4, seg = c & 15;
            cp16(sb + (uint32_t)(j * FROW) * 2 + seg * 16,        kg + j * 128 + seg * 8);
            cp16(sb + (uint32_t)((64 + j) * FROW) * 2 + seg * 16, vg + j * 128 + seg * 8);
        }
        asm volatile("cp.async.commit_group;" ::: "memory");
    };

    // start streaming tile 0 into buf0, stage Q into buf1 meanwhile
    load_tile(0, 0);
    {
        __nv_bfloat16* qb = smx + FBUF;
        for (int i = tid; i < 2048; i += 256) {
            int row = i >> 4, d = (i & 15) * 4;
            float4 f4 = *(const float4*)(qkv + base + (size_t)(qt * 128 + row) * C3_ + h * D_ + d);
            f4.x *= 0.125f; f4.y *= 0.125f; f4.z *= 0.125f; f4.w *= 0.125f;
            uint2 lo; uint2 hi = split4(f4, lo);
            *(uint2*)&qb[row * FROW + d]      = hi;
            *(uint2*)&qb[row * FROW + 64 + d] = lo;
        }
    }
    __syncthreads();

    uint32_t qf[8][4];
    #pragma unroll
    for (int kb = 0; kb < 8; kb++) {
        uint32_t addr = smb0 + FBUF * 2 +
                        (uint32_t)((w * 16 + (lane & 15)) * FROW + kb * 16 + (lane >> 4) * 8) * 2;
        ldsm_x4(qf[kb][0], qf[kb][1], qf[kb][2], qf[kb][3], addr);
    }
    __syncthreads();

    float o[8][4];
    #pragma unroll
    for (int nb = 0; nb < 8; nb++)
        #pragma unroll
        for (int e = 0; e < 4; e++) o[nb][e] = 0.f;
    float m0 = -1e30f, m1 = -1e30f, l0 = 0.f, l1 = 0.f;

    const int qrow_g0 = qt * 128 + w * 16 + (lane >> 2);
    const int nkt = (qt + 1) * 2;

    for (int kt = 0; kt < nkt; kt++) {
        if (kt + 1 < nkt) load_tile((kt + 1) & 1, kt + 1);
        else asm volatile("cp.async.commit_group;" ::: "memory");
        asm volatile("cp.async.wait_group 1;" ::: "memory");
        __syncthreads();

        const uint32_t smb = smb0 + (kt & 1) * (FBUF * 2);

        // ---- S = Q' K'^T ----
        float s[8][4];
        #pragma unroll
        for (int nb = 0; nb < 8; nb++)
            #pragma unroll
            for (int e = 0; e < 4; e++) s[nb][e] = 0.f;

        #pragma unroll
        for (int kb = 0; kb < 12; kb++) {
            int bcol = (kb < 4) ? kb * 16 : ((kb < 8) ? (kb - 4) * 16 : 64 + (kb - 8) * 16);
            const uint32_t* af = (kb < 8) ? qf[kb] : qf[kb - 8];
            #pragma unroll
            for (int nbp = 0; nbp < 4; nbp++) {
                uint32_t r0, r1, r2, r3;
                uint32_t addr = smb +
                    (uint32_t)((nbp * 16 + (lane & 7) + ((lane >> 4) & 1) * 8) * FROW
                               + bcol + ((lane >> 3) & 1) * 8) * 2;
                ldsm_x4(r0, r1, r2, r3, addr);
                mma16816(s[nbp * 2],     af, r0, r1);
                mma16816(s[nbp * 2 + 1], af, r2, r3);
            }
        }

        // ---- causal mask ----
        if (kt * 64 + 63 > qt * 128 + w * 16) {
            #pragma unroll
            for (int nb = 0; nb < 8; nb++) {
                int col = kt * 64 + nb * 8 + (lane & 3) * 2;
                if (col     > qrow_g0)     s[nb][0] = -1e30f;
                if (col + 1 > qrow_g0)     s[nb][1] = -1e30f;
                if (col     > qrow_g0 + 8) s[nb][2] = -1e30f;
                if (col + 1 > qrow_g0 + 8) s[nb][3] = -1e30f;
            }
        }

        // ---- online softmax ----
        float tm0 = -1e30f, tm1 = -1e30f;
        #pragma unroll
        for (int nb = 0; nb < 8; nb++) {
            tm0 = fmaxf(tm0, fmaxf(s[nb][0], s[nb][1]));
            tm1 = fmaxf(tm1, fmaxf(s[nb][2], s[nb][3]));
        }
        tm0 = fmaxf(tm0, __shfl_xor_sync(0xffffffffu, tm0, 1));
        tm0 = fmaxf(tm0, __shfl_xor_sync(0xffffffffu, tm0, 2));
        tm1 = fmaxf(tm1, __shfl_xor_sync(0xffffffffu, tm1, 1));
        tm1 = fmaxf(tm1, __shfl_xor_sync(0xffffffffu, tm1, 2));

        float m0n = fmaxf(m0, tm0), m1n = fmaxf(m1, tm1);
        float corr0 = __expf(m0 - m0n), corr1 = __expf(m1 - m1n);
        m0 = m0n; m1 = m1n;
        l0 *= corr0; l1 *= corr1;

        #pragma unroll
        for (int nb = 0; nb < 8; nb++) {
            s[nb][0] = __expf(s[nb][0] - m0);
            s[nb][1] = __expf(s[nb][1] - m0);
            s[nb][2] = __expf(s[nb][2] - m1);
            s[nb][3] = __expf(s[nb][3] - m1);
            l0 += s[nb][0] + s[nb][1];
            l1 += s[nb][2] + s[nb][3];
            o[nb][0] *= corr0; o[nb][1] *= corr0;
            o[nb][2] *= corr1; o[nb][3] *= corr1;
        }

        // ---- P -> split-bf16 A-fragments ----
        uint32_t Ph[4][4], Pl[4][4];
        #pragma unroll
        for (int kb = 0; kb < 4; kb++) {
            #pragma unroll
            for (int q = 0; q < 4; q++) {
                int nb = kb * 2 + (q >> 1);
                uint32_t pl;
                Ph[kb][q] = split2(s[nb][(q & 1) * 2], s[nb][(q & 1) * 2 + 1], pl);
                Pl[kb][q] = pl;
            }
        }

        // ---- O += P' V' ----
        #pragma unroll
        for (int kb = 0; kb < 12; kb++) {
            int krow = 64 + (kb & 3) * 16;
            int vcol = (kb < 8) ? 0 : 64;
            const uint32_t* af = (kb < 4) ? Ph[kb] : ((kb < 8) ? Pl[kb - 4] : Ph[kb - 8]);
            #pragma unroll
            for (int nbp = 0; nbp < 4; nbp++) {
                uint32_t r0, r1, r2, r3;
                uint32_t addr = smb +
                    (uint32_t)((krow + (lane & 15)) * FROW + vcol + nbp * 16 + (lane >> 4) * 8) * 2;
                ldsm_x4t(r0, r1, r2, r3, addr);
                mma16816(o[nbp * 2],     af, r0, r1);
                mma16816(o[nbp * 2 + 1], af, r2, r3);
            }
        }
        __syncthreads();
    }

    // ---- finalize: normalize + XSA, write split-A3 directly ----
    l0 += __shfl_xor_sync(0xffffffffu, l0, 1);
    l0 += __shfl_xor_sync(0xffffffffu, l0, 2);
    l1 += __shfl_xor_sync(0xffffffffu, l1, 1);
    l1 += __shfl_xor_sync(0xffffffffu, l1, 2);
    float inv0 = 1.f / l0, inv1 = 1.f / l1;

    float2 vr0[8], vr1[8];
    float sov0 = 0.f, svv0 = 0.f, sov1 = 0.f, svv1 = 0.f;
    const float* vb = qkv + base + 2 * C_ + h * D_;
    #pragma unroll
    for (int nb = 0; nb < 8; nb++) {
        int d = nb * 8 + (lane & 3) * 2;
        vr0[nb] = *(const float2*)(vb + (size_t)qrow_g0 * C3_ + d);
        vr1[nb] = *(const float2*)(vb + (size_t)(qrow_g0 + 8) * C3_ + d);
        o[nb][0] *= inv0; o[nb][1] *= inv0; o[nb][2] *= inv1; o[nb][3] *= inv1;
        sov0 += o[nb][0] * vr0[nb].x + o[nb][1] * vr0[nb].y;
        svv0 += vr0[nb].x * vr0[nb].x + vr0[nb].y * vr0[nb].y;
        sov1 += o[nb][2] * vr1[nb].x + o[nb][3] * vr1[nb].y;
        svv1 += vr1[nb].x * vr1[nb].x + vr1[nb].y * vr1[nb].y;
    }
    sov0 += __shfl_xor_sync(0xffffffffu, sov0, 1);
    sov0 += __shfl_xor_sync(0xffffffffu, sov0, 2);
    svv0 += __shfl_xor_sync(0xffffffffu, svv0, 1);
    svv0 += __shfl_xor_sync(0xffffffffu, svv0, 2);
    sov1 += __shfl_xor_sync(0xffffffffu, sov1, 1);
    sov1 += __shfl_xor_sync(0xffffffffu, sov1, 2);
    svv1 += __shfl_xor_sync(0xffffffffu, svv1, 1);
    svv1 += __shfl_xor_sync(0xffffffffu, svv1, 2);

    float mx0 = fmaxf(sqrtf(svv0), 1e-12f);
    float mx1 = fmaxf(sqrtf(svv1), 1e-12f);
    float c0 = sov0 / (mx0 * mx0), c1 = sov1 / (mx1 * mx1);

    __nv_bfloat16* a0 = A3out + (size_t)(b * T_ + qrow_g0) * K3_;
    __nv_bfloat16* a1 = a0 + 8 * K3_;
    #pragma unroll
    for (int nb = 0; nb < 8; nb++) {
        int k = h * D_ + nb * 8 + (lane & 3) * 2;
        float y00 = o[nb][0] - c0 * vr0[nb].x, y01 = o[nb][1] - c0 * vr0[nb].y;
        float y10 = o[nb][2] - c1 * vr1[nb].x, y11 = o[nb][3] - c1 * vr1[nb].y;
        uint32_t lo0; uint32_t hi0 = split2(y00, y01, lo0);
        uint32_t lo1; uint32_t hi1 = split2(y10, y11, lo1);
        *(uint32_t*)(a0 + k)        = hi0;
        *(uint32_t*)(a0 + 1024 + k) = lo0;
        *(uint32_t*)(a0 + 2048 + k) = hi0;
        *(uint32_t*)(a1 + k)        = hi1;
        *(uint32_t*)(a1 + 1024 + k) = lo1;
        *(uint32_t*)(a1 + 2048 + k) = hi1;
    }
}

// ---------------------------------------------------------------------------
extern "C" void kernel_launch(void* const* d_in, const int* in_sizes, int n_in,
                              void* d_out, int out_size)
{
    const float* x  = (const float*)d_in[0];
    const float* Wa = (const float*)d_in[1];
    const float* ba = (const float*)d_in[2];
    const float* Wp = (const float*)d_in[3];
    const float* bp = (const float*)d_in[4];
    float* out = (float*)d_out;

    float* qkv;
    __nv_bfloat16 *A3, *B3, *Kp, *Vp;
    cudaGetSymbolAddress((void**)&qkv, g_qkv);
    cudaGetSymbolAddress((void**)&A3,  g_A3);
    cudaGetSymbolAddress((void**)&B3,  g_B3);
    cudaGetSymbolAddress((void**)&Kp,  g_K);
    cudaGetSymbolAddress((void**)&Vp,  g_V);

    const int M = B_ * T_;
    const int flash_smem = 2 * FBUF * 2;   // 69.6 KB

    static int attr_set = 0;
    if (!attr_set) {
        cudaFuncSetAttribute(flash_hmma, cudaFuncAttributeMaxDynamicSharedMemorySize, flash_smem);
        attr_set = 1;
    }

    prep_W<<<dim3(C3_ / 32, C_ / 32), 256>>>(Wa, B3, C3_);
    split_A<<<(M * C_) / (256 * 8), 256>>>(x, A3);
    hmma_gemm<<<dim3(C3_ / 128, M / 128), 256>>>(A3, B3, ba, qkv, M, C3_, K3_);

    sparsemax_kv<<<(M * H_) / 8, 256>>>(qkv, Kp, Vp);

    flash_hmma<<<dim3(T_ / 128, H_, B_), 256, flash_smem>>>(qkv, Kp, Vp, A3);

    prep_W<<<dim3(C_ / 32, C_ / 32), 256>>>(Wp, B3, C_);
    hmma_gemm<<<dim3(C_ / 128, M / 128), 256>>>(A3, B3, bp, out, M, C_, K3_);
}

// round 8
// speedup vs baseline: 3.9401x; 1.1434x over previous
#include <cuda_runtime.h>
#include <cuda_bf16.h>
#include <math.h>
#include <stdint.h>

#define B_  4
#define T_  2048
#define C_  1024
#define H_  16
#define D_  64
#define C3_ 3072
#define K3_ 3072

typedef unsigned long long u64;

__device__ float g_qkv[(size_t)B_ * T_ * C3_];
__device__ __nv_bfloat16 g_A3[(size_t)B_ * T_ * K3_];
__device__ __nv_bfloat16 g_B3[(size_t)C3_ * K3_];
__device__ __nv_bfloat16 g_K[(size_t)B_ * H_ * T_ * 128];
__device__ __nv_bfloat16 g_V[(size_t)B_ * H_ * T_ * 128];

// ---- helpers ----
__device__ __forceinline__ uint32_t smem_u32(const void* p) {
    uint32_t a;
    asm("{ .reg .u64 t; cvta.to.shared.u64 t, %1; cvt.u32.u64 %0, t; }" : "=r"(a) : "l"(p));
    return a;
}
__device__ __forceinline__ void cp16(uint32_t dst, const void* src) {
    asm volatile("cp.async.cg.shared.global [%0], [%1], 16;" :: "r"(dst), "l"(src));
}
__device__ __forceinline__ void ldsm_x4(uint32_t& r0, uint32_t& r1, uint32_t& r2, uint32_t& r3,
                                        uint32_t addr) {
    asm volatile("ldmatrix.sync.aligned.m8n8.x4.shared.b16 {%0,%1,%2,%3},[%4];"
                 : "=r"(r0), "=r"(r1), "=r"(r2), "=r"(r3) : "r"(addr));
}
__device__ __forceinline__ void ldsm_x4t(uint32_t& r0, uint32_t& r1, uint32_t& r2, uint32_t& r3,
                                         uint32_t addr) {
    asm volatile("ldmatrix.sync.aligned.m8n8.x4.trans.shared.b16 {%0,%1,%2,%3},[%4];"
                 : "=r"(r0), "=r"(r1), "=r"(r2), "=r"(r3) : "r"(addr));
}
__device__ __forceinline__ void mma16816(float* c, const uint32_t* a, uint32_t b0, uint32_t b1) {
    asm volatile(
        "mma.sync.aligned.m16n8k16.row.col.f32.bf16.bf16.f32 "
        "{%0,%1,%2,%3},{%4,%5,%6,%7},{%8,%9},{%0,%1,%2,%3};"
        : "+f"(c[0]), "+f"(c[1]), "+f"(c[2]), "+f"(c[3])
        : "r"(a[0]), "r"(a[1]), "r"(a[2]), "r"(a[3]), "r"(b0), "r"(b1));
}
__device__ __forceinline__ uint32_t pkbf(float lo, float hi) {
    uint32_t r; asm("cvt.rn.bf16x2.f32 %0,%1,%2;" : "=r"(r) : "f"(hi), "f"(lo)); return r;
}
__device__ __forceinline__ uint32_t split2(float a, float b, uint32_t& lo) {
    uint32_t hp = pkbf(a, b);
    float la = a - __uint_as_float(hp << 16);
    float lb = b - __uint_as_float(hp & 0xFFFF0000u);
    lo = pkbf(la, lb);
    return hp;
}
__device__ __forceinline__ uint2 split4(float4 f, uint2& lo) {
    uint32_t l0, l1;
    uint32_t h0 = split2(f.x, f.y, l0);
    uint32_t h1 = split2(f.z, f.w, l1);
    lo = make_uint2(l0, l1);
    return make_uint2(h0, h1);
}

// ---------------------------------------------------------------------------
// split_A: src fp32 [M,1024] -> dst bf16 [M,3072] = [hi|lo|hi]
// ---------------------------------------------------------------------------
__global__ __launch_bounds__(256) void split_A(
    const float* __restrict__ src, __nv_bfloat16* __restrict__ dst)
{
    size_t idx = ((size_t)blockIdx.x * 256 + threadIdx.x) * 8;
    int m = (int)(idx >> 10), k = (int)(idx & 1023);
    float4 f0 = *(const float4*)(src + idx);
    float4 f1 = *(const float4*)(src + idx + 4);
    uint2 l0, l1;
    uint2 h0 = split4(f0, l0);
    uint2 h1 = split4(f1, l1);
    __nv_bfloat16* r = dst + (size_t)m * K3_;
    *(uint4*)(r + k)        = make_uint4(h0.x, h0.y, h1.x, h1.y);
    *(uint4*)(r + 1024 + k) = make_uint4(l0.x, l0.y, l1.x, l1.y);
    *(uint4*)(r + 2048 + k) = make_uint4(h0.x, h0.y, h1.x, h1.y);
}

// ---------------------------------------------------------------------------
// prep_W: W fp32 [1024, N] -> Bo bf16 [N,3072] = [hi|hi|lo]
// ---------------------------------------------------------------------------
__global__ __launch_bounds__(256) void prep_W(
    const float* __restrict__ W, __nv_bfloat16* __restrict__ Bo, int N)
{
    __shared__ float t[32][33];
    int n0 = blockIdx.x * 32, k0 = blockIdx.y * 32;
    {
        int tx = threadIdx.x & 31, ty = threadIdx.x >> 5;
        #pragma unroll
        for (int i = 0; i < 4; i++)
            t[ty + i * 8][tx] = W[(size_t)(k0 + ty + i * 8) * N + n0 + tx];
    }
    __syncthreads();
    int kk = (threadIdx.x & 15) * 2, ny = threadIdx.x >> 4;
    #pragma unroll
    for (int i = 0; i < 2; i++) {
        int n = ny + i * 16;
        uint32_t lp;
        uint32_t hp = split2(t[kk][n], t[kk + 1][n], lp);
        size_t r = (size_t)(n0 + n) * K3_;
        *(uint32_t*)(Bo + r + k0 + kk)        = hp;
        *(uint32_t*)(Bo + r + 1024 + k0 + kk) = hp;
        *(uint32_t*)(Bo + r + 2048 + k0 + kk) = lp;
    }
}

// ---------------------------------------------------------------------------
// HMMA GEMM: 128x128 CTA tile, BK=64, 3-stage cp.async pipeline, dynamic smem.
// ---------------------------------------------------------------------------
#define BK    64
#define ROWE  72     // 64 data + 8 pad (144B stride, conflict-free ldmatrix)
#define NSTG  3
#define OPBYTES (128 * ROWE * 2)          // one operand, one stage

__global__ __launch_bounds__(256) void hmma_gemm(
    const __nv_bfloat16* __restrict__ A, const __nv_bfloat16* __restrict__ Bk,
    const float* __restrict__ bias, float* __restrict__ Cout,
    int M, int N, int K)
{
    extern __shared__ __align__(16) __nv_bfloat16 gsm[];   // NSTG*(A|B)

    const int tid  = threadIdx.x;
    const int lane = tid & 31;
    const int wid  = tid >> 5;
    const int wm   = wid >> 2;
    const int wn   = wid & 3;
    const int m0 = blockIdx.y * 128, n0 = blockIdx.x * 128;

    const uint32_t smb = smem_u32(gsm);

    auto load_tile = [&](int stg, int kt) {
        const __nv_bfloat16* Ag = A + (size_t)m0 * K + kt * BK;
        const __nv_bfloat16* Bg = Bk + (size_t)n0 * K + kt * BK;
        uint32_t sA = smb + stg * (2 * OPBYTES);
        uint32_t sB = sA + OPBYTES;
        #pragma unroll
        for (int it = 0; it < 4; it++) {
            int c = tid + it * 256;            // 0..1023
            int row = c >> 3, seg = c & 7;
            uint32_t doff = (uint32_t)(row * ROWE + seg * 8) * 2;
            cp16(sA + doff, Ag + (size_t)row * K + seg * 8);
            cp16(sB + doff, Bg + (size_t)row * K + seg * 8);
        }
        asm volatile("cp.async.commit_group;" ::: "memory");
    };

    float acc[4][4][4];
    #pragma unroll
    for (int i = 0; i < 4; i++)
        #pragma unroll
        for (int j = 0; j < 4; j++)
            #pragma unroll
            for (int e = 0; e < 4; e++) acc[i][j][e] = 0.f;

    const int nkt = K / BK;   // 48
    load_tile(0, 0);
    load_tile(1, 1);

    const int a_row = wm * 64 + (lane & 15);
    const int a_ko  = (lane >> 4) * 8;
    const int b_row = wn * 32 + (lane & 7) + ((lane >> 4) & 1) * 8;
    const int b_ko  = ((lane >> 3) & 1) * 8;

    int stg = 0;
    for (int kt = 0; kt < nkt; kt++) {
        if (kt + 2 < nkt) {
            int s2 = stg + 2; if (s2 >= NSTG) s2 -= NSTG;
            load_tile(s2, kt + 2);
        } else {
            asm volatile("cp.async.commit_group;" ::: "memory");
        }
        asm volatile("cp.async.wait_group 2;" ::: "memory");
        __syncthreads();

        const uint32_t aT = smb + stg * (2 * OPBYTES);
        const uint32_t bT = aT + OPBYTES;

        #pragma unroll
        for (int ks = 0; ks < 4; ks++) {
            uint32_t af[4][4];
            #pragma unroll
            for (int mi = 0; mi < 4; mi++)
                ldsm_x4(af[mi][0], af[mi][1], af[mi][2], af[mi][3],
                        aT + (uint32_t)((a_row + mi * 16) * ROWE + ks * 16 + a_ko) * 2);
            uint32_t bf[4][2];
            #pragma unroll
            for (int nb = 0; nb < 2; nb++) {
                uint32_t r0, r1, r2, r3;
                ldsm_x4(r0, r1, r2, r3,
                        bT + (uint32_t)((b_row + nb * 16) * ROWE + ks * 16 + b_ko) * 2);
                bf[nb * 2][0] = r0; bf[nb * 2][1] = r1;
                bf[nb * 2 + 1][0] = r2; bf[nb * 2 + 1][1] = r3;
            }
            #pragma unroll
            for (int mi = 0; mi < 4; mi++)
                #pragma unroll
                for (int ni = 0; ni < 4; ni++)
                    mma16816(acc[mi][ni], af[mi], bf[ni][0], bf[ni][1]);
        }
        __syncthreads();
        if (++stg >= NSTG) stg = 0;
    }

    #pragma unroll
    for (int mi = 0; mi < 4; mi++) {
        int row_g = m0 + wm * 64 + mi * 16 + (lane >> 2);
        #pragma unroll
        for (int ni = 0; ni < 4; ni++) {
            int col_g = n0 + wn * 32 + ni * 8 + (lane & 3) * 2;
            float b0 = bias[col_g], b1 = bias[col_g + 1];
            float2 o0 = make_float2(acc[mi][ni][0] + b0, acc[mi][ni][1] + b1);
            float2 o1 = make_float2(acc[mi][ni][2] + b0, acc[mi][ni][3] + b1);
            *(float2*)(Cout + (size_t)row_g * N + col_g) = o0;
            *(float2*)(Cout + (size_t)(row_g + 8) * N + col_g) = o1;
        }
    }
}

// ---------------------------------------------------------------------------
// Sparsemax over K head-dim + fused split of K AND V into bf16 [hi|lo] rows.
// ---------------------------------------------------------------------------
__global__ __launch_bounds__(256) void sparsemax_kv(
    const float* __restrict__ qkv,
    __nv_bfloat16* __restrict__ Ko, __nv_bfloat16* __restrict__ Vo)
{
    const int lane = threadIdx.x & 31;
    const int wrp  = threadIdx.x >> 5;
    const size_t row = (size_t)blockIdx.x * 8 + wrp;
    const size_t bt  = row >> 4;
    const int    h   = (int)(row & 15);
    const int    b   = (int)(bt >> 11);
    const int    t   = (int)(bt & 2047);

    const float* pk = qkv + bt * C3_ + C_ + h * D_;
    float2 z = *(const float2*)(pk + 2 * lane);
    float v0 = z.x, v1 = z.y;

    #pragma unroll
    for (int k = 2; k <= 64; k <<= 1) {
        #pragma unroll
        for (int j = k >> 1; j > 0; j >>= 1) {
            if (j < 32) {
                float p0 = __shfl_xor_sync(0xffffffffu, v0, j);
                float p1 = __shfl_xor_sync(0xffffffffu, v1, j);
                bool lower = (lane & j) == 0;
                bool up0 = (lane & k) != 0;
                bool up1 = ((lane + 32) & k) != 0;
                v0 = (lower == up0) ? fminf(v0, p0) : fmaxf(v0, p0);
                v1 = (lower == up1) ? fminf(v1, p1) : fmaxf(v1, p1);
            } else {
                float a = fmaxf(v0, v1), bmin = fminf(v0, v1);
                v0 = a; v1 = bmin;
            }
        }
    }

    float c0 = v0;
    #pragma unroll
    for (int o = 1; o < 32; o <<= 1) {
        float tt = __shfl_up_sync(0xffffffffu, c0, o);
        if (lane >= o) c0 += tt;
    }
    float c1 = v1;
    #pragma unroll
    for (int o = 1; o < 32; o <<= 1) {
        float tt = __shfl_up_sync(0xffffffffu, c1, o);
        if (lane >= o) c1 += tt;
    }
    c1 += __shfl_sync(0xffffffffu, c0, 31);

    bool s0 = 1.f + (float)(lane + 1)  * v0 > c0;
    bool s1 = 1.f + (float)(lane + 33) * v1 > c1;
    int rho = __popc(__ballot_sync(0xffffffffu, s0)) +
              __popc(__ballot_sync(0xffffffffu, s1));
    int ridx = rho - 1;
    float csA = __shfl_sync(0xffffffffu, c0, ridx & 31);
    float csB = __shfl_sync(0xffffffffu, c1, ridx & 31);
    float cs  = (ridx < 32) ? csA : csB;
    float tau = (cs - 1.f) / (float)rho;

    float k0 = fmaxf(z.x - tau, 0.f), k1 = fmaxf(z.y - tau, 0.f);
    uint32_t klo; uint32_t khi = split2(k0, k1, klo);
    __nv_bfloat16* kr = Ko + ((size_t)(b * H_ + h) * T_ + t) * 128;
    *(uint32_t*)(kr + 2 * lane)      = khi;
    *(uint32_t*)(kr + 64 + 2 * lane) = klo;

    float2 vv = *(const float2*)(pk + C_ + 2 * lane);
    uint32_t vlo; uint32_t vhi = split2(vv.x, vv.y, vlo);
    __nv_bfloat16* vr = Vo + ((size_t)(b * H_ + h) * T_ + t) * 128;
    *(uint32_t*)(vr + 2 * lane)      = vhi;
    *(uint32_t*)(vr + 64 + 2 * lane) = vlo;
}

// ---------------------------------------------------------------------------
// Flash attention (LPT ordering: heavy qt blocks first), cp.async K/V,
// fused XSA, epilogue writes split-A3.
// ---------------------------------------------------------------------------
#define FROW 136
#define FBUF (128 * FROW)

__global__ __launch_bounds__(256) void flash_hmma(
    const float* __restrict__ qkv,
    const __nv_bfloat16* __restrict__ Ks, const __nv_bfloat16* __restrict__ Vs,
    __nv_bfloat16* __restrict__ A3out)
{
    extern __shared__ __align__(16) __nv_bfloat16 smx[];

    const int tid  = threadIdx.x;
    const int lane = tid & 31;
    const int w    = tid >> 5;
    const int qt = (int)gridDim.x - 1 - (int)blockIdx.x;   // heavy blocks first
    const int h = blockIdx.y, b = blockIdx.z;
    const size_t base = (size_t)b * T_ * C3_;

    const __nv_bfloat16* Kb = Ks + (size_t)(b * H_ + h) * T_ * 128;
    const __nv_bfloat16* Vb = Vs + (size_t)(b * H_ + h) * T_ * 128;
    const uint32_t smb0 = smem_u32(smx);

    auto load_tile = [&](int buf, int kt) {
        const __nv_bfloat16* kg = Kb + (size_t)kt * 64 * 128;
        const __nv_bfloat16* vg = Vb + (size_t)kt * 64 * 128;
        uint32_t sb = smb0 + buf * (FBUF * 2);
        #pragma unroll
        for (int it = 0; it < 4; it++) {
            int c = tid + it * 256;
            int j = c >> 4, seg = c & 15;
            cp16(sb + (uint32_t)(j * FROW) * 2 + seg * 16,        kg + j * 128 + seg * 8);
            cp16(sb + (uint32_t)((64 + j) * FROW) * 2 + seg * 16, vg + j * 128 + seg * 8);
        }
        asm volatile("cp.async.commit_group;" ::: "memory");
    };

    load_tile(0, 0);
    {
        __nv_bfloat16* qb = smx + FBUF;
        for (int i = tid; i < 2048; i += 256) {
            int row = i >> 4, d = (i & 15) * 4;
            float4 f4 = *(const float4*)(qkv + base + (size_t)(qt * 128 + row) * C3_ + h * D_ + d);
            f4.x *= 0.125f; f4.y *= 0.125f; f4.z *= 0.125f; f4.w *= 0.125f;
            uint2 lo; uint2 hi = split4(f4, lo);
            *(uint2*)&qb[row * FROW + d]      = hi;
            *(uint2*)&qb[row * FROW + 64 + d] = lo;
        }
    }
    __syncthreads();

    uint32_t qf[8][4];
    #pragma unroll
    for (int kb = 0; kb < 8; kb++) {
        uint32_t addr = smb0 + FBUF * 2 +
                        (uint32_t)((w * 16 + (lane & 15)) * FROW + kb * 16 + (lane >> 4) * 8) * 2;
        ldsm_x4(qf[kb][0], qf[kb][1], qf[kb][2], qf[kb][3], addr);
    }
    __syncthreads();

    float o[8][4];
    #pragma unroll
    for (int nb = 0; nb < 8; nb++)
        #pragma unroll
        for (int e = 0; e < 4; e++) o[nb][e] = 0.f;
    float m0 = -1e30f, m1 = -1e30f, l0 = 0.f, l1 = 0.f;

    const int qrow_g0 = qt * 128 + w * 16 + (lane >> 2);
    const int nkt = (qt + 1) * 2;

    for (int kt = 0; kt < nkt; kt++) {
        if (kt + 1 < nkt) load_tile((kt + 1) & 1, kt + 1);
        else asm volatile("cp.async.commit_group;" ::: "memory");
        asm volatile("cp.async.wait_group 1;" ::: "memory");
        __syncthreads();

        const uint32_t smb = smb0 + (kt & 1) * (FBUF * 2);

        float s[8][4];
        #pragma unroll
        for (int nb = 0; nb < 8; nb++)
            #pragma unroll
            for (int e = 0; e < 4; e++) s[nb][e] = 0.f;

        #pragma unroll
        for (int kb = 0; kb < 12; kb++) {
            int bcol = (kb < 4) ? kb * 16 : ((kb < 8) ? (kb - 4) * 16 : 64 + (kb - 8) * 16);
            const uint32_t* af = (kb < 8) ? qf[kb] : qf[kb - 8];
            #pragma unroll
            for (int nbp = 0; nbp < 4; nbp++) {
                uint32_t r0, r1, r2, r3;
                uint32_t addr = smb +
                    (uint32_t)((nbp * 16 + (lane & 7) + ((lane >> 4) & 1) * 8) * FROW
                               + bcol + ((lane >> 3) & 1) * 8) * 2;
                ldsm_x4(r0, r1, r2, r3, addr);
                mma16816(s[nbp * 2],     af, r0, r1);
                mma16816(s[nbp * 2 + 1], af, r2, r3);
            }
        }

        if (kt * 64 + 63 > qt * 128 + w * 16) {
            #pragma unroll
            for (int nb = 0; nb < 8; nb++) {
                int col = kt * 64 + nb * 8 + (lane & 3) * 2;
                if (col     > qrow_g0)     s[nb][0] = -1e30f;
                if (col + 1 > qrow_g0)     s[nb][1] = -1e30f;
                if (col     > qrow_g0 + 8) s[nb][2] = -1e30f;
                if (col + 1 > qrow_g0 + 8) s[nb][3] = -1e30f;
            }
        }

        float tm0 = -1e30f, tm1 = -1e30f;
        #pragma unroll
        for (int nb = 0; nb < 8; nb++) {
            tm0 = fmaxf(tm0, fmaxf(s[nb][0], s[nb][1]));
            tm1 = fmaxf(tm1, fmaxf(s[nb][2], s[nb][3]));
        }
        tm0 = fmaxf(tm0, __shfl_xor_sync(0xffffffffu, tm0, 1));
        tm0 = fmaxf(tm0, __shfl_xor_sync(0xffffffffu, tm0, 2));
        tm1 = fmaxf(tm1, __shfl_xor_sync(0xffffffffu, tm1, 1));
        tm1 = fmaxf(tm1, __shfl_xor_sync(0xffffffffu, tm1, 2));

        float m0n = fmaxf(m0, tm0), m1n = fmaxf(m1, tm1);
        float corr0 = __expf(m0 - m0n), corr1 = __expf(m1 - m1n);
        m0 = m0n; m1 = m1n;
        l0 *= corr0; l1 *= corr1;

        #pragma unroll
        for (int nb = 0; nb < 8; nb++) {
            s[nb][0] = __expf(s[nb][0] - m0);
            s[nb][1] = __expf(s[nb][1] - m0);
            s[nb][2] = __expf(s[nb][2] - m1);
            s[nb][3] = __expf(s[nb][3] - m1);
            l0 += s[nb][0] + s[nb][1];
            l1 += s[nb][2] + s[nb][3];
            o[nb][0] *= corr0; o[nb][1] *= corr0;
            o[nb][2] *= corr1; o[nb][3] *= corr1;
        }

        uint32_t Ph[4][4], Pl[4][4];
        #pragma unroll
        for (int kb = 0; kb < 4; kb++) {
            #pragma unroll
            for (int q = 0; q < 4; q++) {
                int nb = kb * 2 + (q >> 1);
                uint32_t pl;
                Ph[kb][q] = split2(s[nb][(q & 1) * 2], s[nb][(q & 1) * 2 + 1], pl);
                Pl[kb][q] = pl;
            }
        }

        #pragma unroll
        for (int kb = 0; kb < 12; kb++) {
            int krow = 64 + (kb & 3) * 16;
            int vcol = (kb < 8) ? 0 : 64;
            const uint32_t* af = (kb < 4) ? Ph[kb] : ((kb < 8) ? Pl[kb - 4] : Ph[kb - 8]);
            #pragma unroll
            for (int nbp = 0; nbp < 4; nbp++) {
                uint32_t r0, r1, r2, r3;
                uint32_t addr = smb +
                    (uint32_t)((krow + (lane & 15)) * FROW + vcol + nbp * 16 + (lane >> 4) * 8) * 2;
                ldsm_x4t(r0, r1, r2, r3, addr);
                mma16816(o[nbp * 2],     af, r0, r1);
                mma16816(o[nbp * 2 + 1], af, r2, r3);
            }
        }
        __syncthreads();
    }

    l0 += __shfl_xor_sync(0xffffffffu, l0, 1);
    l0 += __shfl_xor_sync(0xffffffffu, l0, 2);
    l1 += __shfl_xor_sync(0xffffffffu, l1, 1);
    l1 += __shfl_xor_sync(0xffffffffu, l1, 2);
    float inv0 = 1.f / l0, inv1 = 1.f / l1;

    float2 vr0[8], vr1[8];
    float sov0 = 0.f, svv0 = 0.f, sov1 = 0.f, svv1 = 0.f;
    const float* vb = qkv + base + 2 * C_ + h * D_;
    #pragma unroll
    for (int nb = 0; nb < 8; nb++) {
        int d = nb * 8 + (lane & 3) * 2;
        vr0[nb] = *(const float2*)(vb + (size_t)qrow_g0 * C3_ + d);
        vr1[nb] = *(const float2*)(vb + (size_t)(qrow_g0 + 8) * C3_ + d);
        o[nb][0] *= inv0; o[nb][1] *= inv0; o[nb][2] *= inv1; o[nb][3] *= inv1;
        sov0 += o[nb][0] * vr0[nb].x + o[nb][1] * vr0[nb].y;
        svv0 += vr0[nb].x * vr0[nb].x + vr0[nb].y * vr0[nb].y;
        sov1 += o[nb][2] * vr1[nb].x + o[nb][3] * vr1[nb].y;
        svv1 += vr1[nb].x * vr1[nb].x + vr1[nb].y * vr1[nb].y;
    }
    sov0 += __shfl_xor_sync(0xffffffffu, sov0, 1);
    sov0 += __shfl_xor_sync(0xffffffffu, sov0, 2);
    svv0 += __shfl_xor_sync(0xffffffffu, svv0, 1);
    svv0 += __shfl_xor_sync(0xffffffffu, svv0, 2);
    sov1 += __shfl_xor_sync(0xffffffffu, sov1, 1);
    sov1 += __shfl_xor_sync(0xffffffffu, sov1, 2);
    svv1 += __shfl_xor_sync(0xffffffffu, svv1, 1);
    svv1 += __shfl_xor_sync(0xffffffffu, svv1, 2);

    float mx0 = fmaxf(sqrtf(svv0), 1e-12f);
    float mx1 = fmaxf(sqrtf(svv1), 1e-12f);
    float c0 = sov0 / (mx0 * mx0), c1 = sov1 / (mx1 * mx1);

    __nv_bfloat16* a0 = A3out + (size_t)(b * T_ + qrow_g0) * K3_;
    __nv_bfloat16* a1 = a0 + 8 * K3_;
    #pragma unroll
    for (int nb = 0; nb < 8; nb++) {
        int k = h * D_ + nb * 8 + (lane & 3) * 2;
        float y00 = o[nb][0] - c0 * vr0[nb].x, y01 = o[nb][1] - c0 * vr0[nb].y;
        float y10 = o[nb][2] - c1 * vr1[nb].x, y11 = o[nb][3] - c1 * vr1[nb].y;
        uint32_t lo0; uint32_t hi0 = split2(y00, y01, lo0);
        uint32_t lo1; uint32_t hi1 = split2(y10, y11, lo1);
        *(uint32_t*)(a0 + k)        = hi0;
        *(uint32_t*)(a0 + 1024 + k) = lo0;
        *(uint32_t*)(a0 + 2048 + k) = hi0;
        *(uint32_t*)(a1 + k)        = hi1;
        *(uint32_t*)(a1 + 1024 + k) = lo1;
        *(uint32_t*)(a1 + 2048 + k) = hi1;
    }
}

// ---------------------------------------------------------------------------
extern "C" void kernel_launch(void* const* d_in, const int* in_sizes, int n_in,
                              void* d_out, int out_size)
{
    const float* x  = (const float*)d_in[0];
    const float* Wa = (const float*)d_in[1];
    const float* ba = (const float*)d_in[2];
    const float* Wp = (const float*)d_in[3];
    const float* bp = (const float*)d_in[4];
    float* out = (float*)d_out;

    float* qkv;
    __nv_bfloat16 *A3, *B3, *Kp, *Vp;
    cudaGetSymbolAddress((void**)&qkv, g_qkv);
    cudaGetSymbolAddress((void**)&A3,  g_A3);
    cudaGetSymbolAddress((void**)&B3,  g_B3);
    cudaGetSymbolAddress((void**)&Kp,  g_K);
    cudaGetSymbolAddress((void**)&Vp,  g_V);

    const int M = B_ * T_;
    const int flash_smem = 2 * FBUF * 2;            // 69.6 KB
    const int gemm_smem  = NSTG * 2 * OPBYTES;      // 110.6 KB

    static int attr_set = 0;
    if (!attr_set) {
        cudaFuncSetAttribute(flash_hmma, cudaFuncAttributeMaxDynamicSharedMemorySize, flash_smem);
        cudaFuncSetAttribute(hmma_gemm,  cudaFuncAttributeMaxDynamicSharedMemorySize, gemm_smem);
        attr_set = 1;
    }

    prep_W<<<dim3(C3_ / 32, C_ / 32), 256>>>(Wa, B3, C3_);
    split_A<<<(M * C_) / (256 * 8), 256>>>(x, A3);
    hmma_gemm<<<dim3(C3_ / 128, M / 128), 256, gemm_smem>>>(A3, B3, ba, qkv, M, C3_, K3_);

    sparsemax_kv<<<(M * H_) / 8, 256>>>(qkv, Kp, Vp);

    flash_hmma<<<dim3(T_ / 128, H_, B_), 256, flash_smem>>>(qkv, Kp, Vp, A3);

    prep_W<<<dim3(C_ / 32, C_ / 32), 256>>>(Wp, B3, C_);
    hmma_gemm<<<dim3(C_ / 128, M / 128), 256, gemm_smem>>>(A3, B3, bp, out, M, C_, K3_);
}